// round 14
// baseline (speedup 1.0000x reference)
#include <cuda_runtime.h>
#include <cuda_fp16.h>
#include <math.h>
#include <stdint.h>
#include <stddef.h>

// ---------------------------------------------------------------------------
// Problem constants
// ---------------------------------------------------------------------------
#define B_   4
#define S_   4096
#define T_   77
#define D_   1280
#define DT_  768
#define H_   8
#define HD_  160
#define RAD_ 64
#define M_BS (B_*S_)   // 16384
#define M_BT (B_*T_)   // 308
#define OFF_ ((size_t)M_BS * D_)

typedef __half fp16;

// ---------------------------------------------------------------------------
// Device scratch
// ---------------------------------------------------------------------------
__device__ float g_q  [M_BS * D_];
__device__ float g_k  [M_BT * D_];
__device__ float g_v  [M_BT * D_];

__device__ fp16 g_hs_hi [M_BS * D_];
__device__ fp16 g_hs_lo [M_BS * D_];
__device__ fp16 g_fg_hi [M_BS * D_];
__device__ fp16 g_fg_lo [M_BS * D_];
__device__ fp16 g_f0_hi [M_BS * D_];
__device__ fp16 g_f0_lo [M_BS * D_];
__device__ fp16 g_f1_hi [M_BS * D_];
__device__ fp16 g_f1_lo [M_BS * D_];
__device__ fp16 g_enc_hi[M_BT * DT_];
__device__ fp16 g_enc_lo[M_BT * DT_];
__device__ fp16 g_wq [D_ * D_];
__device__ fp16 g_wo [D_ * D_];
__device__ fp16 g_wk [D_ * DT_];
__device__ fp16 g_wv [D_ * DT_];
__device__ fp16 g_dw0[RAD_ * D_];
__device__ fp16 g_dw1[RAD_ * D_];
__device__ fp16 g_uw0[D_ * RAD_];
__device__ fp16 g_uw1[D_ * RAD_];
__device__ fp16 g_H  [2 * M_BS * RAD_];

// ---------------------------------------------------------------------------
// helpers
// ---------------------------------------------------------------------------
__device__ __forceinline__ unsigned smem_u32(const void* p) {
    return (unsigned)__cvta_generic_to_shared(p);
}
__device__ __forceinline__ void cpa16(unsigned dst, const fp16* src, int sz) {
    asm volatile("cp.async.cg.shared.global [%0], [%1], 16, %2;\n"
                 :: "r"(dst), "l"(src), "r"(sz));
}
__device__ __forceinline__ void ldmx4(unsigned& r0, unsigned& r1, unsigned& r2, unsigned& r3, unsigned addr) {
    asm volatile("ldmatrix.sync.aligned.m8n8.x4.shared.b16 {%0,%1,%2,%3}, [%4];"
                 : "=r"(r0), "=r"(r1), "=r"(r2), "=r"(r3) : "r"(addr));
}
__device__ __forceinline__ void mma_f16(float* d, const unsigned* a, const unsigned* b) {
    asm volatile(
        "mma.sync.aligned.m16n8k16.row.col.f32.f16.f16.f32 "
        "{%0,%1,%2,%3}, {%4,%5,%6,%7}, {%8,%9}, {%0,%1,%2,%3};"
        : "+f"(d[0]), "+f"(d[1]), "+f"(d[2]), "+f"(d[3])
        : "r"(a[0]), "r"(a[1]), "r"(a[2]), "r"(a[3]), "r"(b[0]), "r"(b[1]));
}
__device__ __forceinline__ void split_f16(float x, fp16& hi, fp16& lo) {
    hi = __float2half_rn(x);
    lo = __float2half_rn(x - __half2float(hi));
}
__device__ __forceinline__ float gelu_exact(float x) {
    return 0.5f * x * (1.f + erff(x * 0.7071067811865475f));
}

// ---------------------------------------------------------------------------
// prep: all converts + LoRA folds fused (region-dispatched)
// ---------------------------------------------------------------------------
#define HS_C   5242880L
#define ENC_C  59136L
#define WQ_C   409600L
#define AD_C   20480L
#define WK_N   983040L
#define WO_N   1638400L
#define PREP_TOT (HS_C + ENC_C + WQ_C + 4*AD_C + 2*WK_N + WO_N)

__device__ __forceinline__ void cvt2_v4(const float* x, fp16* hi, fp16* lo, long i) {
    float4 v = *(const float4*)(x + i);
    fp16 h0,l0,h1,l1,h2,l2,h3,l3;
    split_f16(v.x,h0,l0); split_f16(v.y,h1,l1); split_f16(v.z,h2,l2); split_f16(v.w,h3,l3);
    hi[i]=h0; hi[i+1]=h1; hi[i+2]=h2; hi[i+3]=h3;
    lo[i]=l0; lo[i+1]=l1; lo[i+2]=l2; lo[i+3]=l3;
}
__device__ __forceinline__ void cvt1_v4(const float* x, fp16* w, long i) {
    float4 v = *(const float4*)(x + i);
    w[i]   = __float2half_rn(v.x); w[i+1] = __float2half_rn(v.y);
    w[i+2] = __float2half_rn(v.z); w[i+3] = __float2half_rn(v.w);
}
__device__ __forceinline__ void fold1(const float* W, const float* A, const float* Bm,
                                      fp16* w, int K, long i) {
    int n = (int)(i / K);
    int k = (int)(i - (long)n * K);
    float acc = W[i];
#pragma unroll
    for (int r = 0; r < 4; r++)
        acc += 0.25f * Bm[n * 4 + r] * A[r * K + k];
    w[i] = __float2half_rn(acc);
}

__global__ void prep_kernel(
    const float* __restrict__ hs, const float* __restrict__ enc, const float* __restrict__ Wq,
    const float* __restrict__ a0dW, const float* __restrict__ a1dW,
    const float* __restrict__ a0uW, const float* __restrict__ a1uW,
    const float* __restrict__ Wk, const float* __restrict__ lkA, const float* __restrict__ lkB,
    const float* __restrict__ Wv, const float* __restrict__ lvA, const float* __restrict__ lvB,
    const float* __restrict__ Wo, const float* __restrict__ loA, const float* __restrict__ loB,
    fp16* hsh, fp16* hsl, fp16* ench, fp16* encl, fp16* wq,
    fp16* dw0, fp16* dw1, fp16* uw0, fp16* uw1,
    fp16* wk, fp16* wv, fp16* wo)
{
    long gid = (long)blockIdx.x * 256 + threadIdx.x;
    if (gid < HS_C)  { cvt2_v4(hs,  hsh,  hsl,  gid * 4); return; }
    gid -= HS_C;
    if (gid < ENC_C) { cvt2_v4(enc, ench, encl, gid * 4); return; }
    gid -= ENC_C;
    if (gid < WQ_C)  { cvt1_v4(Wq, wq, gid * 4); return; }
    gid -= WQ_C;
    if (gid < AD_C)  { cvt1_v4(a0dW, dw0, gid * 4); return; }
    gid -= AD_C;
    if (gid < AD_C)  { cvt1_v4(a1dW, dw1, gid * 4); return; }
    gid -= AD_C;
    if (gid < AD_C)  { cvt1_v4(a0uW, uw0, gid * 4); return; }
    gid -= AD_C;
    if (gid < AD_C)  { cvt1_v4(a1uW, uw1, gid * 4); return; }
    gid -= AD_C;
    if (gid < WK_N)  { fold1(Wk, lkA, lkB, wk, DT_, gid); return; }
    gid -= WK_N;
    if (gid < WK_N)  { fold1(Wv, lvA, lvB, wv, DT_, gid); return; }
    gid -= WK_N;
    if (gid < WO_N)  { fold1(Wo, loA, loB, wo, D_, gid); return; }
}

// ---------------------------------------------------------------------------
// Main tensor-core GEMM: C[M,N] = A[M,K] @ W[N,K]^T (+bias), 2-pass fp16 split
// ---------------------------------------------------------------------------
#define SMSH   72
#define PANELB (128 * SMSH * 2)
#define STAGEB (3 * PANELB)
#define GDYN   (2 * STAGEB)

__global__ void __launch_bounds__(256, 2) mma_gemm_kernel(
    const fp16* __restrict__ Ahi, const fp16* __restrict__ Alo,
    const fp16* __restrict__ Bw,  const fp16* __restrict__ Bw2,
    const float* __restrict__ bias, float* __restrict__ C, float* __restrict__ C2,
    int M, int N, int K)
{
    extern __shared__ fp16 smem_dyn[];
    const unsigned sbase = smem_u32(smem_dyn);

    const fp16* Bsel = (blockIdx.z == 0) ? Bw : Bw2;
    float*      Csel = (blockIdx.z == 0) ? C  : C2;

    const int tid  = threadIdx.x;
    const int warp = tid >> 5;
    const int lane = tid & 31;
    const int bm = blockIdx.y * 128;
    const int bn = blockIdx.x * 128;
    const int wm = (warp >> 1) * 32;
    const int wn = (warp & 1) * 64;

    unsigned dsta[4];
    int a_sz[4];
    size_t a_src[4], b_src[4];
#pragma unroll
    for (int j = 0; j < 4; j++) {
        int c   = tid + 256 * j;
        int row = c >> 3;
        int sl  = c & 7;
        dsta[j] = sbase + (unsigned)(row * SMSH + sl * 8) * 2;
        int gm = bm + row;
        a_sz[j]  = (gm < M) ? 16 : 0;
        int gm_c = (gm < M) ? gm : (M > 0 ? M - 1 : 0);
        a_src[j] = (size_t)gm_c * K + sl * 8;
        b_src[j] = (size_t)(bn + row) * K + sl * 8;
    }

    unsigned a_addr[2], b_addr[4];
#pragma unroll
    for (int i = 0; i < 2; i++) {
        int row = wm + i * 16 + (lane & 15);
        int ko  = (lane >> 4) * 8;
        a_addr[i] = sbase + (unsigned)(row * SMSH + ko) * 2;
    }
#pragma unroll
    for (int jp = 0; jp < 4; jp++) {
        int grp = lane >> 3, lr = lane & 7;
        int row = wn + jp * 16 + ((grp >> 1) * 8) + lr;
        int ko  = (grp & 1) * 8;
        b_addr[jp] = sbase + 2u * PANELB + (unsigned)(row * SMSH + ko) * 2;
    }

    float acc[2][8][4];
#pragma unroll
    for (int i = 0; i < 2; i++)
#pragma unroll
        for (int j = 0; j < 8; j++)
#pragma unroll
            for (int r = 0; r < 4; r++) acc[i][j][r] = 0.f;

    const int KT = K >> 6;

    auto load_stage = [&](int st, int kt) {
        const unsigned so = (unsigned)st * STAGEB;
        const int kb = kt * 64;
#pragma unroll
        for (int j = 0; j < 4; j++) {
            cpa16(dsta[j] + so,              Ahi  + a_src[j] + kb, a_sz[j]);
            cpa16(dsta[j] + so + PANELB,     Alo  + a_src[j] + kb, a_sz[j]);
            cpa16(dsta[j] + so + 2u*PANELB,  Bsel + b_src[j] + kb, 16);
        }
        asm volatile("cp.async.commit_group;\n");
    };

    load_stage(0, 0);

    for (int kt = 0; kt < KT; kt++) {
        asm volatile("cp.async.wait_group 0;\n" ::: "memory");
        __syncthreads();

        if (kt + 1 < KT) load_stage((kt + 1) & 1, kt + 1);

        const unsigned so = (unsigned)(kt & 1) * STAGEB;
#pragma unroll
        for (int ks = 0; ks < 4; ks++) {
            const unsigned kso = so + ks * 32;
            unsigned ah[2][4], al[2][4];
#pragma unroll
            for (int i = 0; i < 2; i++) {
                ldmx4(ah[i][0], ah[i][1], ah[i][2], ah[i][3], a_addr[i] + kso);
                ldmx4(al[i][0], al[i][1], al[i][2], al[i][3], a_addr[i] + kso + PANELB);
            }
#pragma unroll
            for (int jp = 0; jp < 4; jp++) {
                unsigned bw[2][2];
                ldmx4(bw[0][0], bw[0][1], bw[1][0], bw[1][1], b_addr[jp] + kso);
#pragma unroll
                for (int jj = 0; jj < 2; jj++) {
                    int j = jp * 2 + jj;
                    mma_f16(acc[0][j], ah[0], bw[jj]);
                    mma_f16(acc[1][j], ah[1], bw[jj]);
                }
#pragma unroll
                for (int jj = 0; jj < 2; jj++) {
                    int j = jp * 2 + jj;
                    mma_f16(acc[0][j], al[0], bw[jj]);
                    mma_f16(acc[1][j], al[1], bw[jj]);
                }
            }
        }
        __syncthreads();
    }

#pragma unroll
    for (int i = 0; i < 2; i++) {
        int r0 = bm + wm + i * 16 + (lane >> 2);
#pragma unroll
        for (int j = 0; j < 8; j++) {
            int col = bn + wn + j * 8 + (lane & 3) * 2;
            float b0 = bias ? bias[col] : 0.f;
            float b1 = bias ? bias[col + 1] : 0.f;
            if (r0 < M) {
                float2 v = make_float2(acc[i][j][0] + b0, acc[i][j][1] + b1);
                *(float2*)(Csel + (size_t)r0 * N + col) = v;
            }
            if (r0 + 8 < M) {
                float2 v = make_float2(acc[i][j][2] + b0, acc[i][j][3] + b1);
                *(float2*)(Csel + (size_t)(r0 + 8) * N + col) = v;
            }
        }
    }
}

// ---------------------------------------------------------------------------
// Adapter down-proj GEMM: H[M,64] = gelu( X[M,1280] @ dW[64,1280]^T + db )
// ---------------------------------------------------------------------------
#define BPANELB (64 * SMSH * 2)
#define STAGE_D (2 * PANELB + BPANELB)
#define GDYN_D  (2 * STAGE_D)

__global__ void __launch_bounds__(256, 2) adapter_down_kernel(
    const fp16* __restrict__ F0h, const fp16* __restrict__ F0l,
    const fp16* __restrict__ F1h, const fp16* __restrict__ F1l,
    const fp16* __restrict__ dw0, const fp16* __restrict__ dw1,
    const float* __restrict__ db0, const float* __restrict__ db1,
    fp16* __restrict__ Hbuf)
{
    extern __shared__ fp16 smem_dyn[];
    const unsigned sbase = smem_u32(smem_dyn);

    const int z = blockIdx.z;
    const fp16* Ah = z ? F1h : F0h;
    const fp16* Al = z ? F1l : F0l;
    const fp16* Bw = z ? dw1 : dw0;
    const float* db = z ? db1 : db0;
    fp16* Hout = Hbuf + (size_t)z * M_BS * RAD_;

    const int tid  = threadIdx.x;
    const int warp = tid >> 5;
    const int lane = tid & 31;
    const int bm = blockIdx.y * 128;
    const int K = D_;

    unsigned dsta[4];
    size_t a_src[4];
#pragma unroll
    for (int j = 0; j < 4; j++) {
        int c   = tid + 256 * j;
        int row = c >> 3;
        int sl  = c & 7;
        dsta[j] = sbase + (unsigned)(row * SMSH + sl * 8) * 2;
        a_src[j] = (size_t)(bm + row) * K + sl * 8;
    }
    unsigned dstb[2];
    size_t b_src[2];
#pragma unroll
    for (int j = 0; j < 2; j++) {
        int c   = tid + 256 * j;
        int row = c >> 3;
        int sl  = c & 7;
        dstb[j] = sbase + 2u * PANELB + (unsigned)(row * SMSH + sl * 8) * 2;
        b_src[j] = (size_t)row * K + sl * 8;
    }

    const int wm = (warp >> 1) * 32;
    const int wn = (warp & 1) * 32;

    unsigned a_addr[2], b_addr[2];
#pragma unroll
    for (int i = 0; i < 2; i++) {
        int row = wm + i * 16 + (lane & 15);
        int ko  = (lane >> 4) * 8;
        a_addr[i] = sbase + (unsigned)(row * SMSH + ko) * 2;
    }
#pragma unroll
    for (int jp = 0; jp < 2; jp++) {
        int grp = lane >> 3, lr = lane & 7;
        int row = wn + jp * 16 + ((grp >> 1) * 8) + lr;
        int ko  = (grp & 1) * 8;
        b_addr[jp] = sbase + 2u * PANELB + (unsigned)(row * SMSH + ko) * 2;
    }

    float acc[2][4][4];
#pragma unroll
    for (int i = 0; i < 2; i++)
#pragma unroll
        for (int j = 0; j < 4; j++)
#pragma unroll
            for (int r = 0; r < 4; r++) acc[i][j][r] = 0.f;

    const int KT = K >> 6;

    auto load_stage = [&](int st, int kt) {
        const unsigned so = (unsigned)st * STAGE_D;
        const int kb = kt * 64;
#pragma unroll
        for (int j = 0; j < 4; j++) {
            cpa16(dsta[j] + so,          Ah + a_src[j] + kb, 16);
            cpa16(dsta[j] + so + PANELB, Al + a_src[j] + kb, 16);
        }
#pragma unroll
        for (int j = 0; j < 2; j++)
            cpa16(dstb[j] + so, Bw + b_src[j] + kb, 16);
        asm volatile("cp.async.commit_group;\n");
    };

    load_stage(0, 0);

    for (int kt = 0; kt < KT; kt++) {
        asm volatile("cp.async.wait_group 0;\n" ::: "memory");
        __syncthreads();

        if (kt + 1 < KT) load_stage((kt + 1) & 1, kt + 1);

        const unsigned so = (unsigned)(kt & 1) * STAGE_D;
#pragma unroll
        for (int ks = 0; ks < 4; ks++) {
            const unsigned kso = so + ks * 32;
            unsigned ah[2][4], al[2][4];
#pragma unroll
            for (int i = 0; i < 2; i++) {
                ldmx4(ah[i][0], ah[i][1], ah[i][2], ah[i][3], a_addr[i] + kso);
                ldmx4(al[i][0], al[i][1], al[i][2], al[i][3], a_addr[i] + kso + PANELB);
            }
#pragma unroll
            for (int jp = 0; jp < 2; jp++) {
                unsigned bw[2][2];
                ldmx4(bw[0][0], bw[0][1], bw[1][0], bw[1][1], b_addr[jp] + kso);
#pragma unroll
                for (int jj = 0; jj < 2; jj++) {
                    int j = jp * 2 + jj;
                    mma_f16(acc[0][j], ah[0], bw[jj]);
                    mma_f16(acc[1][j], ah[1], bw[jj]);
                }
#pragma unroll
                for (int jj = 0; jj < 2; jj++) {
                    int j = jp * 2 + jj;
                    mma_f16(acc[0][j], al[0], bw[jj]);
                    mma_f16(acc[1][j], al[1], bw[jj]);
                }
            }
        }
        __syncthreads();
    }

#pragma unroll
    for (int i = 0; i < 2; i++) {
        int r0 = bm + wm + i * 16 + (lane >> 2);
#pragma unroll
        for (int j = 0; j < 4; j++) {
            int col = wn + j * 8 + (lane & 3) * 2;
            float b0 = db[col], b1 = db[col + 1];
            {
                float v0 = gelu_exact(acc[i][j][0] + b0);
                float v1 = gelu_exact(acc[i][j][1] + b1);
                __half2 hv = __floats2half2_rn(v0, v1);
                *(__half2*)(Hout + (size_t)r0 * RAD_ + col) = hv;
            }
            {
                float v0 = gelu_exact(acc[i][j][2] + b0);
                float v1 = gelu_exact(acc[i][j][3] + b1);
                __half2 hv = __floats2half2_rn(v0, v1);
                *(__half2*)(Hout + (size_t)(r0 + 8) * RAD_ + col) = hv;
            }
        }
    }
}

// ---------------------------------------------------------------------------
// Adapter up-proj GEMM: out[M,1280] = X + ( H[M,64] @ uW[1280,64]^T + ub )
// ---------------------------------------------------------------------------
__global__ void __launch_bounds__(256, 2) adapter_up_kernel(
    const fp16* __restrict__ Hbuf,
    const fp16* __restrict__ uw0, const fp16* __restrict__ uw1,
    const float* __restrict__ ub0, const float* __restrict__ ub1,
    const fp16* __restrict__ F0h, const fp16* __restrict__ F0l,
    const fp16* __restrict__ F1h, const fp16* __restrict__ F1l,
    float* __restrict__ out)
{
    __shared__ fp16 smem_up[2 * 128 * SMSH];
    const unsigned sbase = smem_u32(smem_up);

    const int z = blockIdx.z;
    const fp16* A  = Hbuf + (size_t)z * M_BS * RAD_;
    const fp16* Bw = z ? uw1 : uw0;
    const float* ub = z ? ub1 : ub0;
    const fp16* Fh = z ? F1h : F0h;
    const fp16* Fl = z ? F1l : F0l;
    float* C = out + (size_t)(z + 1) * OFF_;

    const int tid  = threadIdx.x;
    const int warp = tid >> 5;
    const int lane = tid & 31;
    const int bm = blockIdx.y * 128;
    const int bn = blockIdx.x * 128;

#pragma unroll
    for (int j = 0; j < 4; j++) {
        int c   = tid + 256 * j;
        int row = c >> 3;
        int sl  = c & 7;
        *(uint4*)(smem_up + row * SMSH + sl * 8) =
            *(const uint4*)(A + (size_t)(bm + row) * RAD_ + sl * 8);
        *(uint4*)(smem_up + 128 * SMSH + row * SMSH + sl * 8) =
            *(const uint4*)(Bw + (size_t)(bn + row) * RAD_ + sl * 8);
    }
    __syncthreads();

    const int wm = (warp >> 1) * 32;
    const int wn = (warp & 1) * 64;

    unsigned a_addr[2], b_addr[4];
#pragma unroll
    for (int i = 0; i < 2; i++) {
        int row = wm + i * 16 + (lane & 15);
        int ko  = (lane >> 4) * 8;
        a_addr[i] = sbase + (unsigned)(row * SMSH + ko) * 2;
    }
#pragma unroll
    for (int jp = 0; jp < 4; jp++) {
        int grp = lane >> 3, lr = lane & 7;
        int row = wn + jp * 16 + ((grp >> 1) * 8) + lr;
        int ko  = (grp & 1) * 8;
        b_addr[jp] = sbase + (unsigned)(128 * SMSH + row * SMSH + ko) * 2;
    }

    float acc[2][8][4];
#pragma unroll
    for (int i = 0; i < 2; i++)
#pragma unroll
        for (int j = 0; j < 8; j++)
#pragma unroll
            for (int r = 0; r < 4; r++) acc[i][j][r] = 0.f;

#pragma unroll
    for (int ks = 0; ks < 4; ks++) {
        const unsigned kso = ks * 32;
        unsigned ah[2][4];
#pragma unroll
        for (int i = 0; i < 2; i++)
            ldmx4(ah[i][0], ah[i][1], ah[i][2], ah[i][3], a_addr[i] + kso);
#pragma unroll
        for (int jp = 0; jp < 4; jp++) {
            unsigned bw[2][2];
            ldmx4(bw[0][0], bw[0][1], bw[1][0], bw[1][1], b_addr[jp] + kso);
#pragma unroll
            for (int jj = 0; jj < 2; jj++) {
                int j = jp * 2 + jj;
                mma_f16(acc[0][j], ah[0], bw[jj]);
                mma_f16(acc[1][j], ah[1], bw[jj]);
            }
        }
    }

#pragma unroll
    for (int i = 0; i < 2; i++) {
        int r0 = bm + wm + i * 16 + (lane >> 2);
#pragma unroll
        for (int j = 0; j < 8; j++) {
            int col = bn + wn + j * 8 + (lane & 3) * 2;
            float u0 = ub[col], u1 = ub[col + 1];
#pragma unroll
            for (int rr = 0; rr < 2; rr++) {
                int r = r0 + rr * 8;
                __half2 xh = *(const __half2*)(Fh + (size_t)r * D_ + col);
                __half2 xl = *(const __half2*)(Fl + (size_t)r * D_ + col);
                float x0 = __half2float(__low2half(xh)) + __half2float(__low2half(xl));
                float x1 = __half2float(__high2half(xh)) + __half2float(__high2half(xl));
                float2 v = make_float2(acc[i][j][rr*2+0] + u0 + x0,
                                       acc[i][j][rr*2+1] + u1 + x1);
                *(float2*)(C + (size_t)r * D_ + col) = v;
            }
        }
    }
}

// ---------------------------------------------------------------------------
// Attention, shuffle-free: lane = key.
// Smem: Kt[d][t] (stride KST=TPAD+1, conflict-free), Vs[t][d] row-major,
// qT[d][s] pre-scaled (stride 68, float4 broadcast), P[warp][t][4q].
// Score loop: per d -> 1 bcast float4 + NS scalar LDS + 4*NS FFMA. No shfl.
// V loop: per t -> 1 bcast float4 (P) + 5 LDS + 20 FFMA. No shfl.
// ---------------------------------------------------------------------------
template<int TKV>
__global__ void __launch_bounds__(256) attn_kernel_t(
    const float* __restrict__ q, const float* __restrict__ k,
    const float* __restrict__ v, const int* __restrict__ toks,
    int maybe64, fp16* __restrict__ outH, fp16* __restrict__ outL)
{
    constexpr int NS   = (TKV + 31) / 32;
    constexpr int TPAD = NS * 32;
    constexpr int KST  = TPAD + 1;   // odd stride -> conflict-free transpose stores
    constexpr int QST  = 68;         // q stride (mult of 4 for float4, %32=4)

    extern __shared__ float sm[];
    float* Kt = sm;                          // [HD_ * KST]
    float* Vs = Kt + HD_ * KST;              // [TKV * HD_]
    float* qT = Vs + TKV * HD_;              // [HD_ * QST]
    float* Ps = qT + HD_ * QST;              // [8 * TPAD * 4]

    const int b  = blockIdx.z;
    const int h  = blockIdx.y;
    const int s0 = blockIdx.x * 64;
    const int tid = threadIdx.x;
    const float scale = 0.07905694150420949f;
    const unsigned FULL = 0xffffffffu;

    int is64 = 0;
    if (toks && maybe64)
        is64 = (toks[1] == 0 && toks[3] == 0 && toks[5] == 0 && toks[7] == 0);

    // --- stage K (transposed) and V (row-major) ---
    for (int i = tid; i < TKV * HD_; i += 256) {
        int t = i / HD_;
        int d = i - t * HD_;
        int trow = t;
        if (toks) trow = is64 ? toks[2 * t] : toks[t];
        size_t gidx = ((size_t)b * T_ + trow) * D_ + h * HD_ + d;
        float kv = k[gidx];
        Kt[d * KST + t] = kv;
        Vs[i] = v[gidx];
    }
    // zero-pad Kt for t in [TKV, TPAD)
    constexpr int PADW = TPAD - TKV;
    for (int i = tid; i < HD_ * PADW; i += 256) {
        int d = i / PADW;
        int t = TKV + (i - d * PADW);
        Kt[d * KST + t] = 0.f;
    }
    // stage qT (pre-scaled): 64 rows x 160
    {
        const float* qb = q + ((size_t)b * S_ + s0) * D_ + h * HD_;
        for (int i = tid; i < 64 * HD_; i += 256) {
            int r = i / HD_;
            int d = i - r * HD_;
            qT[d * QST + r] = qb[(size_t)r * D_ + d] * scale;
        }
    }
    __syncthreads();

    const int warp = tid >> 5;
    const int lane = tid & 31;
    float* Pw = Ps + warp * TPAD * 4;

#pragma unroll
    for (int g = 0; g < 2; g++) {
        const int sl4 = warp * 8 + g * 4;               // local query row base
        size_t base0 = ((size_t)b * S_ + s0 + sl4) * D_ + h * HD_;

        // --- scores: sc[i][n] = sum_d q_i[d] * K[t=lane+32n][d] ---
        float sc[4][NS];
#pragma unroll
        for (int i = 0; i < 4; i++)
#pragma unroll
            for (int n = 0; n < NS; n++) sc[i][n] = 0.f;

#pragma unroll 4
        for (int d = 0; d < HD_; d++) {
            float4 qv = *(const float4*)(qT + d * QST + sl4);
            float kk[NS];
#pragma unroll
            for (int n = 0; n < NS; n++) kk[n] = Kt[d * KST + lane + 32 * n];
#pragma unroll
            for (int n = 0; n < NS; n++) {
                sc[0][n] += qv.x * kk[n];
                sc[1][n] += qv.y * kk[n];
                sc[2][n] += qv.z * kk[n];
                sc[3][n] += qv.w * kk[n];
            }
        }

        // --- softmax over keys (distributed across lanes) ---
        float m[4];
#pragma unroll
        for (int i = 0; i < 4; i++) {
            m[i] = -1e30f;
#pragma unroll
            for (int n = 0; n < NS; n++)
                if (n * 32 + lane < TKV) m[i] = fmaxf(m[i], sc[i][n]);
        }
#pragma unroll
        for (int off = 16; off; off >>= 1) {
#pragma unroll
            for (int i = 0; i < 4; i++)
                m[i] = fmaxf(m[i], __shfl_xor_sync(FULL, m[i], off));
        }
        float ssum[4];
#pragma unroll
        for (int i = 0; i < 4; i++) {
            ssum[i] = 0.f;
#pragma unroll
            for (int n = 0; n < NS; n++) {
                sc[i][n] = (n * 32 + lane < TKV) ? expf(sc[i][n] - m[i]) : 0.f;
                ssum[i] += sc[i][n];
            }
        }
#pragma unroll
        for (int off = 16; off; off >>= 1) {
#pragma unroll
            for (int i = 0; i < 4; i++)
                ssum[i] += __shfl_xor_sync(FULL, ssum[i], off);
        }
#pragma unroll
        for (int i = 0; i < 4; i++) {
            float inv = 1.f / ssum[i];
#pragma unroll
            for (int n = 0; n < NS; n++) sc[i][n] *= inv;
        }

        // --- publish P to smem: Pw[t][i] ---
#pragma unroll
        for (int n = 0; n < NS; n++) {
            int t = lane + 32 * n;
#pragma unroll
            for (int i = 0; i < 4; i++)
                Pw[t * 4 + i] = sc[i][n];
        }
        __syncwarp();

        // --- weighted V accumulation (P via float4 broadcast) ---
        float o[4][5];
#pragma unroll
        for (int i = 0; i < 4; i++)
#pragma unroll
            for (int j = 0; j < 5; j++) o[i][j] = 0.f;

#pragma unroll 2
        for (int t = 0; t < TKV; t++) {
            float4 pv = *(const float4*)(Pw + t * 4);
            const float* vr = Vs + t * HD_;
            float vv[5];
#pragma unroll
            for (int j = 0; j < 5; j++) vv[j] = vr[lane + 32 * j];
#pragma unroll
            for (int j = 0; j < 5; j++) {
                o[0][j] += pv.x * vv[j];
                o[1][j] += pv.y * vv[j];
                o[2][j] += pv.z * vv[j];
                o[3][j] += pv.w * vv[j];
            }
        }

#pragma unroll
        for (int i = 0; i < 4; i++) {
#pragma unroll
            for (int j = 0; j < 5; j++) {
                fp16 hh, ll; split_f16(o[i][j], hh, ll);
                outH[base0 + (size_t)i * D_ + lane + 32 * j] = hh;
                outL[base0 + (size_t)i * D_ + lane + 32 * j] = ll;
            }
        }
        __syncwarp();   // Pw reused next group
    }
}

// per-instantiation dynamic smem size (bytes)
template<int TKV>
constexpr size_t attn_smem() {
    constexpr int NS   = (TKV + 31) / 32;
    constexpr int TPAD = NS * 32;
    constexpr int KST  = TPAD + 1;
    return (size_t)(HD_ * KST + TKV * HD_ + HD_ * 68 + 8 * TPAD * 4) * sizeof(float);
}

// ---------------------------------------------------------------------------
// Launch
// ---------------------------------------------------------------------------
extern "C" void kernel_launch(void* const* d_in, const int* in_sizes, int n_in,
                              void* d_out, int out_size)
{
    const float* hs    = (const float*)d_in[0];
    const float* enc   = (const float*)d_in[1];
    const int*   e0    = (const int*)  d_in[2];
    const int*   e1    = (const int*)  d_in[3];
    const float* Wq    = (const float*)d_in[4];
    const float* Wk    = (const float*)d_in[5];
    const float* Wv    = (const float*)d_in[6];
    const float* Wo    = (const float*)d_in[7];
    const float* bo    = (const float*)d_in[8];
    const float* lkA   = (const float*)d_in[9];
    const float* lkB   = (const float*)d_in[10];
    const float* lvA   = (const float*)d_in[11];
    const float* lvB   = (const float*)d_in[12];
    const float* loA   = (const float*)d_in[13];
    const float* loB   = (const float*)d_in[14];
    const float* a0dW  = (const float*)d_in[15];
    const float* a0db  = (const float*)d_in[16];
    const float* a0uW  = (const float*)d_in[17];
    const float* a0ub  = (const float*)d_in[18];
    const float* a1dW  = (const float*)d_in[19];
    const float* a1db  = (const float*)d_in[20];
    const float* a1uW  = (const float*)d_in[21];
    const float* a1ub  = (const float*)d_in[22];

    float *qp, *kp, *vp;
    fp16 *hsh, *hsl, *fgh, *fgl, *f0h, *f0l, *f1h, *f1l, *ench, *encl;
    fp16 *wq, *wo, *wk, *wv, *dw0, *dw1, *uw0, *uw1, *Hb;
    cudaGetSymbolAddress((void**)&qp,   g_q);
    cudaGetSymbolAddress((void**)&kp,   g_k);
    cudaGetSymbolAddress((void**)&vp,   g_v);
    cudaGetSymbolAddress((void**)&hsh,  g_hs_hi);
    cudaGetSymbolAddress((void**)&hsl,  g_hs_lo);
    cudaGetSymbolAddress((void**)&fgh,  g_fg_hi);
    cudaGetSymbolAddress((void**)&fgl,  g_fg_lo);
    cudaGetSymbolAddress((void**)&f0h,  g_f0_hi);
    cudaGetSymbolAddress((void**)&f0l,  g_f0_lo);
    cudaGetSymbolAddress((void**)&f1h,  g_f1_hi);
    cudaGetSymbolAddress((void**)&f1l,  g_f1_lo);
    cudaGetSymbolAddress((void**)&ench, g_enc_hi);
    cudaGetSymbolAddress((void**)&encl, g_enc_lo);
    cudaGetSymbolAddress((void**)&wq,   g_wq);
    cudaGetSymbolAddress((void**)&wo,   g_wo);
    cudaGetSymbolAddress((void**)&wk,   g_wk);
    cudaGetSymbolAddress((void**)&wv,   g_wv);
    cudaGetSymbolAddress((void**)&dw0,  g_dw0);
    cudaGetSymbolAddress((void**)&dw1,  g_dw1);
    cudaGetSymbolAddress((void**)&uw0,  g_uw0);
    cudaGetSymbolAddress((void**)&uw1,  g_uw1);
    cudaGetSymbolAddress((void**)&Hb,   g_H);

    float* out = (float*)d_out;

    cudaFuncSetAttribute(mma_gemm_kernel,
                         cudaFuncAttributeMaxDynamicSharedMemorySize, GDYN);
    cudaFuncSetAttribute(adapter_down_kernel,
                         cudaFuncAttributeMaxDynamicSharedMemorySize, GDYN_D);
    cudaFuncSetAttribute(attn_kernel_t<77>,
                         cudaFuncAttributeMaxDynamicSharedMemorySize, (int)attn_smem<77>());
    cudaFuncSetAttribute(attn_kernel_t<8>,
                         cudaFuncAttributeMaxDynamicSharedMemorySize, (int)attn_smem<8>());
    cudaFuncSetAttribute(attn_kernel_t<12>,
                         cudaFuncAttributeMaxDynamicSharedMemorySize, (int)attn_smem<12>());

    // 1: fused prep
    long prep_blocks = (PREP_TOT + 255) / 256;
    prep_kernel<<<(unsigned)prep_blocks, 256>>>(
        hs, enc, Wq, a0dW, a1dW, a0uW, a1uW,
        Wk, lkA, lkB, Wv, lvA, lvB, Wo, loA, loB,
        hsh, hsl, ench, encl, wq, dw0, dw1, uw0, uw1, wk, wv, wo);

    // 2: q projection
    dim3 gq(D_ / 128, M_BS / 128, 1);
    mma_gemm_kernel<<<gq, 256, GDYN>>>(hsh, hsl, wq, nullptr, nullptr,
                                       qp, nullptr, M_BS, D_, D_);

    // 3: merged k+v projections
    dim3 gkv(D_ / 128, (M_BT + 127) / 128, 2);
    mma_gemm_kernel<<<gkv, 256, GDYN>>>(ench, encl, wk, wv, nullptr,
                                        kp, vp, M_BT, D_, DT_);

    // 4: global attention  <-- ncu capture slot
    dim3 ga(S_ / 64, H_, B_);
    attn_kernel_t<77><<<ga, 256, attn_smem<77>()>>>(
        qp, kp, vp, nullptr, 0, fgh, fgl);

    // 5-6: entity attentions
    attn_kernel_t<8><<<ga, 256, attn_smem<8>()>>>(
        qp, kp, vp, e0, 1, f0h, f0l);
    attn_kernel_t<12><<<ga, 256, attn_smem<12>()>>>(
        qp, kp, vp, e1, 0, f1h, f1l);

    // 7: adapter down
    dim3 gd(1, M_BS / 128, 2);
    adapter_down_kernel<<<gd, 256, GDYN_D>>>(f0h, f0l, f1h, f1l,
                                             dw0, dw1, a0db, a1db, Hb);

    // 8: adapter up
    dim3 gu(D_ / 128, M_BS / 128, 2);
    adapter_up_kernel<<<gu, 256>>>(Hb, uw0, uw1, a0ub, a1ub,
                                   f0h, f0l, f1h, f1l, out);

    // 9: output projection
    mma_gemm_kernel<<<gq, 256, GDYN>>>(fgh, fgl, wo, nullptr, bo,
                                       out, nullptr, M_BS, D_, D_);
}

// round 15
// speedup vs baseline: 1.0029x; 1.0029x over previous
#include <cuda_runtime.h>
#include <cuda_fp16.h>
#include <math.h>
#include <stdint.h>
#include <stddef.h>

// ---------------------------------------------------------------------------
// Problem constants
// ---------------------------------------------------------------------------
#define B_   4
#define S_   4096
#define T_   77
#define D_   1280
#define DT_  768
#define H_   8
#define HD_  160
#define RAD_ 64
#define M_BS (B_*S_)   // 16384
#define M_BT (B_*T_)   // 308
#define OFF_ ((size_t)M_BS * D_)

typedef __half fp16;

// ---------------------------------------------------------------------------
// Device scratch
// ---------------------------------------------------------------------------
__device__ float g_q  [M_BS * D_];
__device__ float g_k  [M_BT * D_];
__device__ float g_v  [M_BT * D_];

__device__ fp16 g_hs_hi [M_BS * D_];
__device__ fp16 g_hs_lo [M_BS * D_];
__device__ fp16 g_fg_hi [M_BS * D_];
__device__ fp16 g_fg_lo [M_BS * D_];
__device__ fp16 g_f0_hi [M_BS * D_];
__device__ fp16 g_f0_lo [M_BS * D_];
__device__ fp16 g_f1_hi [M_BS * D_];
__device__ fp16 g_f1_lo [M_BS * D_];
__device__ fp16 g_enc_hi[M_BT * DT_];
__device__ fp16 g_enc_lo[M_BT * DT_];
__device__ fp16 g_wq [D_ * D_];
__device__ fp16 g_wo [D_ * D_];
__device__ fp16 g_wk [D_ * DT_];
__device__ fp16 g_wv [D_ * DT_];
__device__ fp16 g_dw0[RAD_ * D_];
__device__ fp16 g_dw1[RAD_ * D_];
__device__ fp16 g_uw0[D_ * RAD_];
__device__ fp16 g_uw1[D_ * RAD_];
__device__ fp16 g_H  [2 * M_BS * RAD_];

// ---------------------------------------------------------------------------
// helpers
// ---------------------------------------------------------------------------
__device__ __forceinline__ unsigned smem_u32(const void* p) {
    return (unsigned)__cvta_generic_to_shared(p);
}
__device__ __forceinline__ void cpa16(unsigned dst, const fp16* src, int sz) {
    asm volatile("cp.async.cg.shared.global [%0], [%1], 16, %2;\n"
                 :: "r"(dst), "l"(src), "r"(sz));
}
__device__ __forceinline__ void ldmx4(unsigned& r0, unsigned& r1, unsigned& r2, unsigned& r3, unsigned addr) {
    asm volatile("ldmatrix.sync.aligned.m8n8.x4.shared.b16 {%0,%1,%2,%3}, [%4];"
                 : "=r"(r0), "=r"(r1), "=r"(r2), "=r"(r3) : "r"(addr));
}
__device__ __forceinline__ void mma_f16(float* d, const unsigned* a, const unsigned* b) {
    asm volatile(
        "mma.sync.aligned.m16n8k16.row.col.f32.f16.f16.f32 "
        "{%0,%1,%2,%3}, {%4,%5,%6,%7}, {%8,%9}, {%0,%1,%2,%3};"
        : "+f"(d[0]), "+f"(d[1]), "+f"(d[2]), "+f"(d[3])
        : "r"(a[0]), "r"(a[1]), "r"(a[2]), "r"(a[3]), "r"(b[0]), "r"(b[1]));
}
__device__ __forceinline__ void split_f16(float x, fp16& hi, fp16& lo) {
    hi = __float2half_rn(x);
    lo = __float2half_rn(x - __half2float(hi));
}
__device__ __forceinline__ float gelu_exact(float x) {
    return 0.5f * x * (1.f + erff(x * 0.7071067811865475f));
}

// ---------------------------------------------------------------------------
// prep: all converts + LoRA folds fused (region-dispatched)
// ---------------------------------------------------------------------------
#define HS_C   5242880L
#define ENC_C  59136L
#define WQ_C   409600L
#define AD_C   20480L
#define WK_N   983040L
#define WO_N   1638400L
#define PREP_TOT (HS_C + ENC_C + WQ_C + 4*AD_C + 2*WK_N + WO_N)

__device__ __forceinline__ void cvt2_v4(const float* x, fp16* hi, fp16* lo, long i) {
    float4 v = *(const float4*)(x + i);
    fp16 h0,l0,h1,l1,h2,l2,h3,l3;
    split_f16(v.x,h0,l0); split_f16(v.y,h1,l1); split_f16(v.z,h2,l2); split_f16(v.w,h3,l3);
    hi[i]=h0; hi[i+1]=h1; hi[i+2]=h2; hi[i+3]=h3;
    lo[i]=l0; lo[i+1]=l1; lo[i+2]=l2; lo[i+3]=l3;
}
__device__ __forceinline__ void cvt1_v4(const float* x, fp16* w, long i) {
    float4 v = *(const float4*)(x + i);
    w[i]   = __float2half_rn(v.x); w[i+1] = __float2half_rn(v.y);
    w[i+2] = __float2half_rn(v.z); w[i+3] = __float2half_rn(v.w);
}
__device__ __forceinline__ void fold1(const float* W, const float* A, const float* Bm,
                                      fp16* w, int K, long i) {
    int n = (int)(i / K);
    int k = (int)(i - (long)n * K);
    float acc = W[i];
#pragma unroll
    for (int r = 0; r < 4; r++)
        acc += 0.25f * Bm[n * 4 + r] * A[r * K + k];
    w[i] = __float2half_rn(acc);
}

__global__ void prep_kernel(
    const float* __restrict__ hs, const float* __restrict__ enc, const float* __restrict__ Wq,
    const float* __restrict__ a0dW, const float* __restrict__ a1dW,
    const float* __restrict__ a0uW, const float* __restrict__ a1uW,
    const float* __restrict__ Wk, const float* __restrict__ lkA, const float* __restrict__ lkB,
    const float* __restrict__ Wv, const float* __restrict__ lvA, const float* __restrict__ lvB,
    const float* __restrict__ Wo, const float* __restrict__ loA, const float* __restrict__ loB,
    fp16* hsh, fp16* hsl, fp16* ench, fp16* encl, fp16* wq,
    fp16* dw0, fp16* dw1, fp16* uw0, fp16* uw1,
    fp16* wk, fp16* wv, fp16* wo)
{
    long gid = (long)blockIdx.x * 256 + threadIdx.x;
    if (gid < HS_C)  { cvt2_v4(hs,  hsh,  hsl,  gid * 4); return; }
    gid -= HS_C;
    if (gid < ENC_C) { cvt2_v4(enc, ench, encl, gid * 4); return; }
    gid -= ENC_C;
    if (gid < WQ_C)  { cvt1_v4(Wq, wq, gid * 4); return; }
    gid -= WQ_C;
    if (gid < AD_C)  { cvt1_v4(a0dW, dw0, gid * 4); return; }
    gid -= AD_C;
    if (gid < AD_C)  { cvt1_v4(a1dW, dw1, gid * 4); return; }
    gid -= AD_C;
    if (gid < AD_C)  { cvt1_v4(a0uW, uw0, gid * 4); return; }
    gid -= AD_C;
    if (gid < AD_C)  { cvt1_v4(a1uW, uw1, gid * 4); return; }
    gid -= AD_C;
    if (gid < WK_N)  { fold1(Wk, lkA, lkB, wk, DT_, gid); return; }
    gid -= WK_N;
    if (gid < WK_N)  { fold1(Wv, lvA, lvB, wv, DT_, gid); return; }
    gid -= WK_N;
    if (gid < WO_N)  { fold1(Wo, loA, loB, wo, D_, gid); return; }
}

// ---------------------------------------------------------------------------
// Main tensor-core GEMM: C[M,N] = A[M,K] @ W[N,K]^T (+bias), 2-pass fp16 split
// ---------------------------------------------------------------------------
#define SMSH   72
#define PANELB (128 * SMSH * 2)
#define STAGEB (3 * PANELB)
#define GDYN   (2 * STAGEB)

__global__ void __launch_bounds__(256, 2) mma_gemm_kernel(
    const fp16* __restrict__ Ahi, const fp16* __restrict__ Alo,
    const fp16* __restrict__ Bw,  const fp16* __restrict__ Bw2,
    const float* __restrict__ bias, float* __restrict__ C, float* __restrict__ C2,
    int M, int N, int K)
{
    extern __shared__ fp16 smem_dyn[];
    const unsigned sbase = smem_u32(smem_dyn);

    const fp16* Bsel = (blockIdx.z == 0) ? Bw : Bw2;
    float*      Csel = (blockIdx.z == 0) ? C  : C2;

    const int tid  = threadIdx.x;
    const int warp = tid >> 5;
    const int lane = tid & 31;
    const int bm = blockIdx.y * 128;
    const int bn = blockIdx.x * 128;
    const int wm = (warp >> 1) * 32;
    const int wn = (warp & 1) * 64;

    unsigned dsta[4];
    int a_sz[4];
    size_t a_src[4], b_src[4];
#pragma unroll
    for (int j = 0; j < 4; j++) {
        int c   = tid + 256 * j;
        int row = c >> 3;
        int sl  = c & 7;
        dsta[j] = sbase + (unsigned)(row * SMSH + sl * 8) * 2;
        int gm = bm + row;
        a_sz[j]  = (gm < M) ? 16 : 0;
        int gm_c = (gm < M) ? gm : (M > 0 ? M - 1 : 0);
        a_src[j] = (size_t)gm_c * K + sl * 8;
        b_src[j] = (size_t)(bn + row) * K + sl * 8;
    }

    unsigned a_addr[2], b_addr[4];
#pragma unroll
    for (int i = 0; i < 2; i++) {
        int row = wm + i * 16 + (lane & 15);
        int ko  = (lane >> 4) * 8;
        a_addr[i] = sbase + (unsigned)(row * SMSH + ko) * 2;
    }
#pragma unroll
    for (int jp = 0; jp < 4; jp++) {
        int grp = lane >> 3, lr = lane & 7;
        int row = wn + jp * 16 + ((grp >> 1) * 8) + lr;
        int ko  = (grp & 1) * 8;
        b_addr[jp] = sbase + 2u * PANELB + (unsigned)(row * SMSH + ko) * 2;
    }

    float acc[2][8][4];
#pragma unroll
    for (int i = 0; i < 2; i++)
#pragma unroll
        for (int j = 0; j < 8; j++)
#pragma unroll
            for (int r = 0; r < 4; r++) acc[i][j][r] = 0.f;

    const int KT = K >> 6;

    auto load_stage = [&](int st, int kt) {
        const unsigned so = (unsigned)st * STAGEB;
        const int kb = kt * 64;
#pragma unroll
        for (int j = 0; j < 4; j++) {
            cpa16(dsta[j] + so,              Ahi  + a_src[j] + kb, a_sz[j]);
            cpa16(dsta[j] + so + PANELB,     Alo  + a_src[j] + kb, a_sz[j]);
            cpa16(dsta[j] + so + 2u*PANELB,  Bsel + b_src[j] + kb, 16);
        }
        asm volatile("cp.async.commit_group;\n");
    };

    load_stage(0, 0);

    for (int kt = 0; kt < KT; kt++) {
        asm volatile("cp.async.wait_group 0;\n" ::: "memory");
        __syncthreads();

        if (kt + 1 < KT) load_stage((kt + 1) & 1, kt + 1);

        const unsigned so = (unsigned)(kt & 1) * STAGEB;
#pragma unroll
        for (int ks = 0; ks < 4; ks++) {
            const unsigned kso = so + ks * 32;
            unsigned ah[2][4], al[2][4];
#pragma unroll
            for (int i = 0; i < 2; i++) {
                ldmx4(ah[i][0], ah[i][1], ah[i][2], ah[i][3], a_addr[i] + kso);
                ldmx4(al[i][0], al[i][1], al[i][2], al[i][3], a_addr[i] + kso + PANELB);
            }
#pragma unroll
            for (int jp = 0; jp < 4; jp++) {
                unsigned bw[2][2];
                ldmx4(bw[0][0], bw[0][1], bw[1][0], bw[1][1], b_addr[jp] + kso);
#pragma unroll
                for (int jj = 0; jj < 2; jj++) {
                    int j = jp * 2 + jj;
                    mma_f16(acc[0][j], ah[0], bw[jj]);
                    mma_f16(acc[1][j], ah[1], bw[jj]);
                }
#pragma unroll
                for (int jj = 0; jj < 2; jj++) {
                    int j = jp * 2 + jj;
                    mma_f16(acc[0][j], al[0], bw[jj]);
                    mma_f16(acc[1][j], al[1], bw[jj]);
                }
            }
        }
        __syncthreads();
    }

#pragma unroll
    for (int i = 0; i < 2; i++) {
        int r0 = bm + wm + i * 16 + (lane >> 2);
#pragma unroll
        for (int j = 0; j < 8; j++) {
            int col = bn + wn + j * 8 + (lane & 3) * 2;
            float b0 = bias ? bias[col] : 0.f;
            float b1 = bias ? bias[col + 1] : 0.f;
            if (r0 < M) {
                float2 v = make_float2(acc[i][j][0] + b0, acc[i][j][1] + b1);
                *(float2*)(Csel + (size_t)r0 * N + col) = v;
            }
            if (r0 + 8 < M) {
                float2 v = make_float2(acc[i][j][2] + b0, acc[i][j][3] + b1);
                *(float2*)(Csel + (size_t)(r0 + 8) * N + col) = v;
            }
        }
    }
}

// ---------------------------------------------------------------------------
// Adapter down-proj GEMM: H[M,64] = gelu( X[M,1280] @ dW[64,1280]^T + db )
// ---------------------------------------------------------------------------
#define BPANELB (64 * SMSH * 2)
#define STAGE_D (2 * PANELB + BPANELB)
#define GDYN_D  (2 * STAGE_D)

__global__ void __launch_bounds__(256, 2) adapter_down_kernel(
    const fp16* __restrict__ F0h, const fp16* __restrict__ F0l,
    const fp16* __restrict__ F1h, const fp16* __restrict__ F1l,
    const fp16* __restrict__ dw0, const fp16* __restrict__ dw1,
    const float* __restrict__ db0, const float* __restrict__ db1,
    fp16* __restrict__ Hbuf)
{
    extern __shared__ fp16 smem_dyn[];
    const unsigned sbase = smem_u32(smem_dyn);

    const int z = blockIdx.z;
    const fp16* Ah = z ? F1h : F0h;
    const fp16* Al = z ? F1l : F0l;
    const fp16* Bw = z ? dw1 : dw0;
    const float* db = z ? db1 : db0;
    fp16* Hout = Hbuf + (size_t)z * M_BS * RAD_;

    const int tid  = threadIdx.x;
    const int warp = tid >> 5;
    const int lane = tid & 31;
    const int bm = blockIdx.y * 128;
    const int K = D_;

    unsigned dsta[4];
    size_t a_src[4];
#pragma unroll
    for (int j = 0; j < 4; j++) {
        int c   = tid + 256 * j;
        int row = c >> 3;
        int sl  = c & 7;
        dsta[j] = sbase + (unsigned)(row * SMSH + sl * 8) * 2;
        a_src[j] = (size_t)(bm + row) * K + sl * 8;
    }
    unsigned dstb[2];
    size_t b_src[2];
#pragma unroll
    for (int j = 0; j < 2; j++) {
        int c   = tid + 256 * j;
        int row = c >> 3;
        int sl  = c & 7;
        dstb[j] = sbase + 2u * PANELB + (unsigned)(row * SMSH + sl * 8) * 2;
        b_src[j] = (size_t)row * K + sl * 8;
    }

    const int wm = (warp >> 1) * 32;
    const int wn = (warp & 1) * 32;

    unsigned a_addr[2], b_addr[2];
#pragma unroll
    for (int i = 0; i < 2; i++) {
        int row = wm + i * 16 + (lane & 15);
        int ko  = (lane >> 4) * 8;
        a_addr[i] = sbase + (unsigned)(row * SMSH + ko) * 2;
    }
#pragma unroll
    for (int jp = 0; jp < 2; jp++) {
        int grp = lane >> 3, lr = lane & 7;
        int row = wn + jp * 16 + ((grp >> 1) * 8) + lr;
        int ko  = (grp & 1) * 8;
        b_addr[jp] = sbase + 2u * PANELB + (unsigned)(row * SMSH + ko) * 2;
    }

    float acc[2][4][4];
#pragma unroll
    for (int i = 0; i < 2; i++)
#pragma unroll
        for (int j = 0; j < 4; j++)
#pragma unroll
            for (int r = 0; r < 4; r++) acc[i][j][r] = 0.f;

    const int KT = K >> 6;

    auto load_stage = [&](int st, int kt) {
        const unsigned so = (unsigned)st * STAGE_D;
        const int kb = kt * 64;
#pragma unroll
        for (int j = 0; j < 4; j++) {
            cpa16(dsta[j] + so,          Ah + a_src[j] + kb, 16);
            cpa16(dsta[j] + so + PANELB, Al + a_src[j] + kb, 16);
        }
#pragma unroll
        for (int j = 0; j < 2; j++)
            cpa16(dstb[j] + so, Bw + b_src[j] + kb, 16);
        asm volatile("cp.async.commit_group;\n");
    };

    load_stage(0, 0);

    for (int kt = 0; kt < KT; kt++) {
        asm volatile("cp.async.wait_group 0;\n" ::: "memory");
        __syncthreads();

        if (kt + 1 < KT) load_stage((kt + 1) & 1, kt + 1);

        const unsigned so = (unsigned)(kt & 1) * STAGE_D;
#pragma unroll
        for (int ks = 0; ks < 4; ks++) {
            const unsigned kso = so + ks * 32;
            unsigned ah[2][4], al[2][4];
#pragma unroll
            for (int i = 0; i < 2; i++) {
                ldmx4(ah[i][0], ah[i][1], ah[i][2], ah[i][3], a_addr[i] + kso);
                ldmx4(al[i][0], al[i][1], al[i][2], al[i][3], a_addr[i] + kso + PANELB);
            }
#pragma unroll
            for (int jp = 0; jp < 2; jp++) {
                unsigned bw[2][2];
                ldmx4(bw[0][0], bw[0][1], bw[1][0], bw[1][1], b_addr[jp] + kso);
#pragma unroll
                for (int jj = 0; jj < 2; jj++) {
                    int j = jp * 2 + jj;
                    mma_f16(acc[0][j], ah[0], bw[jj]);
                    mma_f16(acc[1][j], ah[1], bw[jj]);
                }
#pragma unroll
                for (int jj = 0; jj < 2; jj++) {
                    int j = jp * 2 + jj;
                    mma_f16(acc[0][j], al[0], bw[jj]);
                    mma_f16(acc[1][j], al[1], bw[jj]);
                }
            }
        }
        __syncthreads();
    }

#pragma unroll
    for (int i = 0; i < 2; i++) {
        int r0 = bm + wm + i * 16 + (lane >> 2);
#pragma unroll
        for (int j = 0; j < 4; j++) {
            int col = wn + j * 8 + (lane & 3) * 2;
            float b0 = db[col], b1 = db[col + 1];
            {
                float v0 = gelu_exact(acc[i][j][0] + b0);
                float v1 = gelu_exact(acc[i][j][1] + b1);
                __half2 hv = __floats2half2_rn(v0, v1);
                *(__half2*)(Hout + (size_t)r0 * RAD_ + col) = hv;
            }
            {
                float v0 = gelu_exact(acc[i][j][2] + b0);
                float v1 = gelu_exact(acc[i][j][3] + b1);
                __half2 hv = __floats2half2_rn(v0, v1);
                *(__half2*)(Hout + (size_t)(r0 + 8) * RAD_ + col) = hv;
            }
        }
    }
}

// ---------------------------------------------------------------------------
// Adapter up-proj GEMM: out[M,1280] = X + ( H[M,64] @ uW[1280,64]^T + ub )
// ---------------------------------------------------------------------------
__global__ void __launch_bounds__(256, 2) adapter_up_kernel(
    const fp16* __restrict__ Hbuf,
    const fp16* __restrict__ uw0, const fp16* __restrict__ uw1,
    const float* __restrict__ ub0, const float* __restrict__ ub1,
    const fp16* __restrict__ F0h, const fp16* __restrict__ F0l,
    const fp16* __restrict__ F1h, const fp16* __restrict__ F1l,
    float* __restrict__ out)
{
    __shared__ fp16 smem_up[2 * 128 * SMSH];
    const unsigned sbase = smem_u32(smem_up);

    const int z = blockIdx.z;
    const fp16* A  = Hbuf + (size_t)z * M_BS * RAD_;
    const fp16* Bw = z ? uw1 : uw0;
    const float* ub = z ? ub1 : ub0;
    const fp16* Fh = z ? F1h : F0h;
    const fp16* Fl = z ? F1l : F0l;
    float* C = out + (size_t)(z + 1) * OFF_;

    const int tid  = threadIdx.x;
    const int warp = tid >> 5;
    const int lane = tid & 31;
    const int bm = blockIdx.y * 128;
    const int bn = blockIdx.x * 128;

#pragma unroll
    for (int j = 0; j < 4; j++) {
        int c   = tid + 256 * j;
        int row = c >> 3;
        int sl  = c & 7;
        *(uint4*)(smem_up + row * SMSH + sl * 8) =
            *(const uint4*)(A + (size_t)(bm + row) * RAD_ + sl * 8);
        *(uint4*)(smem_up + 128 * SMSH + row * SMSH + sl * 8) =
            *(const uint4*)(Bw + (size_t)(bn + row) * RAD_ + sl * 8);
    }
    __syncthreads();

    const int wm = (warp >> 1) * 32;
    const int wn = (warp & 1) * 64;

    unsigned a_addr[2], b_addr[4];
#pragma unroll
    for (int i = 0; i < 2; i++) {
        int row = wm + i * 16 + (lane & 15);
        int ko  = (lane >> 4) * 8;
        a_addr[i] = sbase + (unsigned)(row * SMSH + ko) * 2;
    }
#pragma unroll
    for (int jp = 0; jp < 4; jp++) {
        int grp = lane >> 3, lr = lane & 7;
        int row = wn + jp * 16 + ((grp >> 1) * 8) + lr;
        int ko  = (grp & 1) * 8;
        b_addr[jp] = sbase + (unsigned)(128 * SMSH + row * SMSH + ko) * 2;
    }

    float acc[2][8][4];
#pragma unroll
    for (int i = 0; i < 2; i++)
#pragma unroll
        for (int j = 0; j < 8; j++)
#pragma unroll
            for (int r = 0; r < 4; r++) acc[i][j][r] = 0.f;

#pragma unroll
    for (int ks = 0; ks < 4; ks++) {
        const unsigned kso = ks * 32;
        unsigned ah[2][4];
#pragma unroll
        for (int i = 0; i < 2; i++)
            ldmx4(ah[i][0], ah[i][1], ah[i][2], ah[i][3], a_addr[i] + kso);
#pragma unroll
        for (int jp = 0; jp < 4; jp++) {
            unsigned bw[2][2];
            ldmx4(bw[0][0], bw[0][1], bw[1][0], bw[1][1], b_addr[jp] + kso);
#pragma unroll
            for (int jj = 0; jj < 2; jj++) {
                int j = jp * 2 + jj;
                mma_f16(acc[0][j], ah[0], bw[jj]);
                mma_f16(acc[1][j], ah[1], bw[jj]);
            }
        }
    }

#pragma unroll
    for (int i = 0; i < 2; i++) {
        int r0 = bm + wm + i * 16 + (lane >> 2);
#pragma unroll
        for (int j = 0; j < 8; j++) {
            int col = bn + wn + j * 8 + (lane & 3) * 2;
            float u0 = ub[col], u1 = ub[col + 1];
#pragma unroll
            for (int rr = 0; rr < 2; rr++) {
                int r = r0 + rr * 8;
                __half2 xh = *(const __half2*)(Fh + (size_t)r * D_ + col);
                __half2 xl = *(const __half2*)(Fl + (size_t)r * D_ + col);
                float x0 = __half2float(__low2half(xh)) + __half2float(__low2half(xl));
                float x1 = __half2float(__high2half(xh)) + __half2float(__high2half(xl));
                float2 v = make_float2(acc[i][j][rr*2+0] + u0 + x0,
                                       acc[i][j][rr*2+1] + u1 + x1);
                *(float2*)(C + (size_t)r * D_ + col) = v;
            }
        }
    }
}

// ---------------------------------------------------------------------------
// Attention, shuffle-free, fp16 K/V in smem for 2 CTAs/SM residency.
// Kt2: half2 over d-pairs [HD_/2][TPAD]; Vs: fp16 [TKV][HD_];
// qT: fp32 [HD_][64] pre-scaled (broadcast float4); Ps: fp32 [8][TPAD][4].
// Score loop per d-pair: 2 bcast float4 + NS LDS.32 + NS cvt + 8*NS FFMA.
// ---------------------------------------------------------------------------
template<int TKV>
__global__ void __launch_bounds__(256) attn_kernel_t(
    const float* __restrict__ q, const float* __restrict__ k,
    const float* __restrict__ v, const int* __restrict__ toks,
    int maybe64, fp16* __restrict__ outH, fp16* __restrict__ outL)
{
    constexpr int NS   = (TKV + 31) / 32;
    constexpr int TPAD = NS * 32;
    constexpr int HDP  = HD_ / 2;        // 80 d-pairs
    constexpr int QST  = 64;

    extern __shared__ char smc[];
    fp16*  KtH = (fp16*)smc;                                   // [HDP][TPAD][2] halves
    fp16*  Vsh = (fp16*)(smc + HDP * TPAD * 4);                // [TKV][HD_]
    float* qT  = (float*)(smc + HDP * TPAD * 4 + TKV * HD_ * 2);
    float* Ps  = qT + HD_ * QST;

    const int b  = blockIdx.z;
    const int h  = blockIdx.y;
    const int s0 = blockIdx.x * 64;
    const int tid = threadIdx.x;
    const float scale = 0.07905694150420949f;
    const unsigned FULL = 0xffffffffu;

    int is64 = 0;
    if (toks && maybe64)
        is64 = (toks[1] == 0 && toks[3] == 0 && toks[5] == 0 && toks[7] == 0);

    // --- stage K (fp16, d-pair-major) and V (fp16, row-major) ---
    for (int i = tid; i < TKV * HD_; i += 256) {
        int t = i / HD_;
        int d = i - t * HD_;
        int trow = t;
        if (toks) trow = is64 ? toks[2 * t] : toks[t];
        size_t gidx = ((size_t)b * T_ + trow) * D_ + h * HD_ + d;
        KtH[(d >> 1) * (TPAD * 2) + t * 2 + (d & 1)] = __float2half_rn(k[gidx]);
        Vsh[i] = __float2half_rn(v[gidx]);
    }
    // zero-pad K for t in [TKV, TPAD)
    constexpr int PADW = TPAD - TKV;
    for (int i = tid; i < HD_ * PADW; i += 256) {
        int d = i / PADW;
        int t = TKV + (i - d * PADW);
        KtH[(d >> 1) * (TPAD * 2) + t * 2 + (d & 1)] = __float2half_rn(0.f);
    }
    // stage qT (pre-scaled): 64 rows x 160
    {
        const float* qb = q + ((size_t)b * S_ + s0) * D_ + h * HD_;
        for (int i = tid; i < 64 * HD_; i += 256) {
            int r = i / HD_;
            int d = i - r * HD_;
            qT[d * QST + r] = qb[(size_t)r * D_ + d] * scale;
        }
    }
    __syncthreads();

    const int warp = tid >> 5;
    const int lane = tid & 31;
    float* Pw = Ps + warp * TPAD * 4;
    const __half2* Kt2 = (const __half2*)KtH;

#pragma unroll
    for (int g = 0; g < 2; g++) {
        const int sl4 = warp * 8 + g * 4;
        size_t base0 = ((size_t)b * S_ + s0 + sl4) * D_ + h * HD_;

        float sc[4][NS];
#pragma unroll
        for (int i = 0; i < 4; i++)
#pragma unroll
            for (int n = 0; n < NS; n++) sc[i][n] = 0.f;

#pragma unroll 2
        for (int dp = 0; dp < HDP; dp++) {
            float4 qa = *(const float4*)(qT + (2 * dp)     * QST + sl4);
            float4 qb4 = *(const float4*)(qT + (2 * dp + 1) * QST + sl4);
            float2 kf[NS];
#pragma unroll
            for (int n = 0; n < NS; n++)
                kf[n] = __half22float2(Kt2[dp * TPAD + lane + 32 * n]);
#pragma unroll
            for (int n = 0; n < NS; n++) {
                sc[0][n] += qa.x * kf[n].x + qb4.x * kf[n].y;
                sc[1][n] += qa.y * kf[n].x + qb4.y * kf[n].y;
                sc[2][n] += qa.z * kf[n].x + qb4.z * kf[n].y;
                sc[3][n] += qa.w * kf[n].x + qb4.w * kf[n].y;
            }
        }

        // --- softmax over keys ---
        float m[4];
#pragma unroll
        for (int i = 0; i < 4; i++) {
            m[i] = -1e30f;
#pragma unroll
            for (int n = 0; n < NS; n++)
                if (n * 32 + lane < TKV) m[i] = fmaxf(m[i], sc[i][n]);
        }
#pragma unroll
        for (int off = 16; off; off >>= 1) {
#pragma unroll
            for (int i = 0; i < 4; i++)
                m[i] = fmaxf(m[i], __shfl_xor_sync(FULL, m[i], off));
        }
        float ssum[4];
#pragma unroll
        for (int i = 0; i < 4; i++) {
            ssum[i] = 0.f;
#pragma unroll
            for (int n = 0; n < NS; n++) {
                sc[i][n] = (n * 32 + lane < TKV) ? expf(sc[i][n] - m[i]) : 0.f;
                ssum[i] += sc[i][n];
            }
        }
#pragma unroll
        for (int off = 16; off; off >>= 1) {
#pragma unroll
            for (int i = 0; i < 4; i++)
                ssum[i] += __shfl_xor_sync(FULL, ssum[i], off);
        }
#pragma unroll
        for (int i = 0; i < 4; i++) {
            float inv = 1.f / ssum[i];
#pragma unroll
            for (int n = 0; n < NS; n++) sc[i][n] *= inv;
        }

        // --- publish P ---
#pragma unroll
        for (int n = 0; n < NS; n++) {
            int t = lane + 32 * n;
#pragma unroll
            for (int i = 0; i < 4; i++)
                Pw[t * 4 + i] = sc[i][n];
        }
        __syncwarp();

        // --- weighted V accumulation ---
        float o[4][5];
#pragma unroll
        for (int i = 0; i < 4; i++)
#pragma unroll
            for (int j = 0; j < 5; j++) o[i][j] = 0.f;

#pragma unroll 2
        for (int t = 0; t < TKV; t++) {
            float4 pv = *(const float4*)(Pw + t * 4);
            const fp16* vr = Vsh + t * HD_;
            float vv[5];
#pragma unroll
            for (int j = 0; j < 5; j++) vv[j] = __half2float(vr[lane + 32 * j]);
#pragma unroll
            for (int j = 0; j < 5; j++) {
                o[0][j] += pv.x * vv[j];
                o[1][j] += pv.y * vv[j];
                o[2][j] += pv.z * vv[j];
                o[3][j] += pv.w * vv[j];
            }
        }

#pragma unroll
        for (int i = 0; i < 4; i++) {
#pragma unroll
            for (int j = 0; j < 5; j++) {
                fp16 hh, ll; split_f16(o[i][j], hh, ll);
                outH[base0 + (size_t)i * D_ + lane + 32 * j] = hh;
                outL[base0 + (size_t)i * D_ + lane + 32 * j] = ll;
            }
        }
        __syncwarp();
    }
}

// per-instantiation dynamic smem size (bytes)
template<int TKV>
constexpr size_t attn_smem() {
    constexpr int NS   = (TKV + 31) / 32;
    constexpr int TPAD = NS * 32;
    return (size_t)(HD_ / 2) * TPAD * 4   // K half2
         + (size_t)TKV * HD_ * 2          // V fp16
         + (size_t)HD_ * 64 * 4           // qT fp32
         + (size_t)8 * TPAD * 4 * 4;      // Ps fp32
}

// ---------------------------------------------------------------------------
// Launch
// ---------------------------------------------------------------------------
extern "C" void kernel_launch(void* const* d_in, const int* in_sizes, int n_in,
                              void* d_out, int out_size)
{
    const float* hs    = (const float*)d_in[0];
    const float* enc   = (const float*)d_in[1];
    const int*   e0    = (const int*)  d_in[2];
    const int*   e1    = (const int*)  d_in[3];
    const float* Wq    = (const float*)d_in[4];
    const float* Wk    = (const float*)d_in[5];
    const float* Wv    = (const float*)d_in[6];
    const float* Wo    = (const float*)d_in[7];
    const float* bo    = (const float*)d_in[8];
    const float* lkA   = (const float*)d_in[9];
    const float* lkB   = (const float*)d_in[10];
    const float* lvA   = (const float*)d_in[11];
    const float* lvB   = (const float*)d_in[12];
    const float* loA   = (const float*)d_in[13];
    const float* loB   = (const float*)d_in[14];
    const float* a0dW  = (const float*)d_in[15];
    const float* a0db  = (const float*)d_in[16];
    const float* a0uW  = (const float*)d_in[17];
    const float* a0ub  = (const float*)d_in[18];
    const float* a1dW  = (const float*)d_in[19];
    const float* a1db  = (const float*)d_in[20];
    const float* a1uW  = (const float*)d_in[21];
    const float* a1ub  = (const float*)d_in[22];

    float *qp, *kp, *vp;
    fp16 *hsh, *hsl, *fgh, *fgl, *f0h, *f0l, *f1h, *f1l, *ench, *encl;
    fp16 *wq, *wo, *wk, *wv, *dw0, *dw1, *uw0, *uw1, *Hb;
    cudaGetSymbolAddress((void**)&qp,   g_q);
    cudaGetSymbolAddress((void**)&kp,   g_k);
    cudaGetSymbolAddress((void**)&vp,   g_v);
    cudaGetSymbolAddress((void**)&hsh,  g_hs_hi);
    cudaGetSymbolAddress((void**)&hsl,  g_hs_lo);
    cudaGetSymbolAddress((void**)&fgh,  g_fg_hi);
    cudaGetSymbolAddress((void**)&fgl,  g_fg_lo);
    cudaGetSymbolAddress((void**)&f0h,  g_f0_hi);
    cudaGetSymbolAddress((void**)&f0l,  g_f0_lo);
    cudaGetSymbolAddress((void**)&f1h,  g_f1_hi);
    cudaGetSymbolAddress((void**)&f1l,  g_f1_lo);
    cudaGetSymbolAddress((void**)&ench, g_enc_hi);
    cudaGetSymbolAddress((void**)&encl, g_enc_lo);
    cudaGetSymbolAddress((void**)&wq,   g_wq);
    cudaGetSymbolAddress((void**)&wo,   g_wo);
    cudaGetSymbolAddress((void**)&wk,   g_wk);
    cudaGetSymbolAddress((void**)&wv,   g_wv);
    cudaGetSymbolAddress((void**)&dw0,  g_dw0);
    cudaGetSymbolAddress((void**)&dw1,  g_dw1);
    cudaGetSymbolAddress((void**)&uw0,  g_uw0);
    cudaGetSymbolAddress((void**)&uw1,  g_uw1);
    cudaGetSymbolAddress((void**)&Hb,   g_H);

    float* out = (float*)d_out;

    cudaFuncSetAttribute(mma_gemm_kernel,
                         cudaFuncAttributeMaxDynamicSharedMemorySize, GDYN);
    cudaFuncSetAttribute(adapter_down_kernel,
                         cudaFuncAttributeMaxDynamicSharedMemorySize, GDYN_D);
    cudaFuncSetAttribute(attn_kernel_t<77>,
                         cudaFuncAttributeMaxDynamicSharedMemorySize, (int)attn_smem<77>());
    cudaFuncSetAttribute(attn_kernel_t<8>,
                         cudaFuncAttributeMaxDynamicSharedMemorySize, (int)attn_smem<8>());
    cudaFuncSetAttribute(attn_kernel_t<12>,
                         cudaFuncAttributeMaxDynamicSharedMemorySize, (int)attn_smem<12>());

    // 1: fused prep
    long prep_blocks = (PREP_TOT + 255) / 256;
    prep_kernel<<<(unsigned)prep_blocks, 256>>>(
        hs, enc, Wq, a0dW, a1dW, a0uW, a1uW,
        Wk, lkA, lkB, Wv, lvA, lvB, Wo, loA, loB,
        hsh, hsl, ench, encl, wq, dw0, dw1, uw0, uw1, wk, wv, wo);

    // 2: q projection
    dim3 gq(D_ / 128, M_BS / 128, 1);
    mma_gemm_kernel<<<gq, 256, GDYN>>>(hsh, hsl, wq, nullptr, nullptr,
                                       qp, nullptr, M_BS, D_, D_);

    // 3: merged k+v projections
    dim3 gkv(D_ / 128, (M_BT + 127) / 128, 2);
    mma_gemm_kernel<<<gkv, 256, GDYN>>>(ench, encl, wk, wv, nullptr,
                                        kp, vp, M_BT, D_, DT_);

    // 4: global attention  <-- ncu capture slot
    dim3 ga(S_ / 64, H_, B_);
    attn_kernel_t<77><<<ga, 256, attn_smem<77>()>>>(
        qp, kp, vp, nullptr, 0, fgh, fgl);

    // 5-6: entity attentions
    attn_kernel_t<8><<<ga, 256, attn_smem<8>()>>>(
        qp, kp, vp, e0, 1, f0h, f0l);
    attn_kernel_t<12><<<ga, 256, attn_smem<12>()>>>(
        qp, kp, vp, e1, 0, f1h, f1l);

    // 7: adapter down
    dim3 gd(1, M_BS / 128, 2);
    adapter_down_kernel<<<gd, 256, GDYN_D>>>(f0h, f0l, f1h, f1l,
                                             dw0, dw1, a0db, a1db, Hb);

    // 8: adapter up
    dim3 gu(D_ / 128, M_BS / 128, 2);
    adapter_up_kernel<<<gu, 256>>>(Hb, uw0, uw1, a0ub, a1ub,
                                   f0h, f0l, f1h, f1l, out);

    // 9: output projection
    mma_gemm_kernel<<<gq, 256, GDYN>>>(fgh, fgl, wo, nullptr, bo,
                                       out, nullptr, M_BS, D_, D_);
}

// round 16
// speedup vs baseline: 1.0832x; 1.0801x over previous
#include <cuda_runtime.h>
#include <cuda_fp16.h>
#include <math.h>
#include <stdint.h>
#include <stddef.h>

// ---------------------------------------------------------------------------
// Problem constants
// ---------------------------------------------------------------------------
#define B_   4
#define S_   4096
#define T_   77
#define D_   1280
#define DT_  768
#define H_   8
#define HD_  160
#define RAD_ 64
#define M_BS (B_*S_)   // 16384
#define M_BT (B_*T_)   // 308
#define OFF_ ((size_t)M_BS * D_)

typedef __half fp16;

// ---------------------------------------------------------------------------
// Device scratch
// ---------------------------------------------------------------------------
__device__ float g_q  [M_BS * D_];
__device__ float g_k  [M_BT * D_];
__device__ float g_v  [M_BT * D_];

__device__ fp16 g_hs_hi [M_BS * D_];
__device__ fp16 g_hs_lo [M_BS * D_];
__device__ fp16 g_fg_hi [M_BS * D_];
__device__ fp16 g_fg_lo [M_BS * D_];
__device__ fp16 g_f0_hi [M_BS * D_];
__device__ fp16 g_f0_lo [M_BS * D_];
__device__ fp16 g_f1_hi [M_BS * D_];
__device__ fp16 g_f1_lo [M_BS * D_];
__device__ fp16 g_enc_hi[M_BT * DT_];
__device__ fp16 g_enc_lo[M_BT * DT_];
__device__ fp16 g_wq [D_ * D_];
__device__ fp16 g_wo [D_ * D_];
__device__ fp16 g_wk [D_ * DT_];
__device__ fp16 g_wv [D_ * DT_];
__device__ fp16 g_dw0[RAD_ * D_];
__device__ fp16 g_dw1[RAD_ * D_];
__device__ fp16 g_uw0[D_ * RAD_];
__device__ fp16 g_uw1[D_ * RAD_];
__device__ fp16 g_H  [2 * M_BS * RAD_];

// ---------------------------------------------------------------------------
// helpers
// ---------------------------------------------------------------------------
__device__ __forceinline__ unsigned smem_u32(const void* p) {
    return (unsigned)__cvta_generic_to_shared(p);
}
__device__ __forceinline__ void cpa16(unsigned dst, const fp16* src, int sz) {
    asm volatile("cp.async.cg.shared.global [%0], [%1], 16, %2;\n"
                 :: "r"(dst), "l"(src), "r"(sz));
}
__device__ __forceinline__ void ldmx4(unsigned& r0, unsigned& r1, unsigned& r2, unsigned& r3, unsigned addr) {
    asm volatile("ldmatrix.sync.aligned.m8n8.x4.shared.b16 {%0,%1,%2,%3}, [%4];"
                 : "=r"(r0), "=r"(r1), "=r"(r2), "=r"(r3) : "r"(addr));
}
__device__ __forceinline__ void mma_f16(float* d, const unsigned* a, const unsigned* b) {
    asm volatile(
        "mma.sync.aligned.m16n8k16.row.col.f32.f16.f16.f32 "
        "{%0,%1,%2,%3}, {%4,%5,%6,%7}, {%8,%9}, {%0,%1,%2,%3};"
        : "+f"(d[0]), "+f"(d[1]), "+f"(d[2]), "+f"(d[3])
        : "r"(a[0]), "r"(a[1]), "r"(a[2]), "r"(a[3]), "r"(b[0]), "r"(b[1]));
}
__device__ __forceinline__ void split_f16(float x, fp16& hi, fp16& lo) {
    hi = __float2half_rn(x);
    lo = __float2half_rn(x - __half2float(hi));
}
__device__ __forceinline__ float gelu_exact(float x) {
    return 0.5f * x * (1.f + erff(x * 0.7071067811865475f));
}

// ---------------------------------------------------------------------------
// prep: all converts + LoRA folds fused (region-dispatched)
// ---------------------------------------------------------------------------
#define HS_C   5242880L
#define ENC_C  59136L
#define WQ_C   409600L
#define AD_C   20480L
#define WK_N   983040L
#define WO_N   1638400L
#define PREP_TOT (HS_C + ENC_C + WQ_C + 4*AD_C + 2*WK_N + WO_N)

__device__ __forceinline__ void cvt2_v4(const float* x, fp16* hi, fp16* lo, long i) {
    float4 v = *(const float4*)(x + i);
    fp16 h0,l0,h1,l1,h2,l2,h3,l3;
    split_f16(v.x,h0,l0); split_f16(v.y,h1,l1); split_f16(v.z,h2,l2); split_f16(v.w,h3,l3);
    hi[i]=h0; hi[i+1]=h1; hi[i+2]=h2; hi[i+3]=h3;
    lo[i]=l0; lo[i+1]=l1; lo[i+2]=l2; lo[i+3]=l3;
}
__device__ __forceinline__ void cvt1_v4(const float* x, fp16* w, long i) {
    float4 v = *(const float4*)(x + i);
    w[i]   = __float2half_rn(v.x); w[i+1] = __float2half_rn(v.y);
    w[i+2] = __float2half_rn(v.z); w[i+3] = __float2half_rn(v.w);
}
__device__ __forceinline__ void fold1(const float* W, const float* A, const float* Bm,
                                      fp16* w, int K, long i) {
    int n = (int)(i / K);
    int k = (int)(i - (long)n * K);
    float acc = W[i];
#pragma unroll
    for (int r = 0; r < 4; r++)
        acc += 0.25f * Bm[n * 4 + r] * A[r * K + k];
    w[i] = __float2half_rn(acc);
}

__global__ void prep_kernel(
    const float* __restrict__ hs, const float* __restrict__ enc, const float* __restrict__ Wq,
    const float* __restrict__ a0dW, const float* __restrict__ a1dW,
    const float* __restrict__ a0uW, const float* __restrict__ a1uW,
    const float* __restrict__ Wk, const float* __restrict__ lkA, const float* __restrict__ lkB,
    const float* __restrict__ Wv, const float* __restrict__ lvA, const float* __restrict__ lvB,
    const float* __restrict__ Wo, const float* __restrict__ loA, const float* __restrict__ loB,
    fp16* hsh, fp16* hsl, fp16* ench, fp16* encl, fp16* wq,
    fp16* dw0, fp16* dw1, fp16* uw0, fp16* uw1,
    fp16* wk, fp16* wv, fp16* wo)
{
    long gid = (long)blockIdx.x * 256 + threadIdx.x;
    if (gid < HS_C)  { cvt2_v4(hs,  hsh,  hsl,  gid * 4); return; }
    gid -= HS_C;
    if (gid < ENC_C) { cvt2_v4(enc, ench, encl, gid * 4); return; }
    gid -= ENC_C;
    if (gid < WQ_C)  { cvt1_v4(Wq, wq, gid * 4); return; }
    gid -= WQ_C;
    if (gid < AD_C)  { cvt1_v4(a0dW, dw0, gid * 4); return; }
    gid -= AD_C;
    if (gid < AD_C)  { cvt1_v4(a1dW, dw1, gid * 4); return; }
    gid -= AD_C;
    if (gid < AD_C)  { cvt1_v4(a0uW, uw0, gid * 4); return; }
    gid -= AD_C;
    if (gid < AD_C)  { cvt1_v4(a1uW, uw1, gid * 4); return; }
    gid -= AD_C;
    if (gid < WK_N)  { fold1(Wk, lkA, lkB, wk, DT_, gid); return; }
    gid -= WK_N;
    if (gid < WK_N)  { fold1(Wv, lvA, lvB, wv, DT_, gid); return; }
    gid -= WK_N;
    if (gid < WO_N)  { fold1(Wo, loA, loB, wo, D_, gid); return; }
}

// ---------------------------------------------------------------------------
// Main tensor-core GEMM: C[M,N] = A[M,K] @ W[N,K]^T (+bias), 2-pass fp16 split
// ---------------------------------------------------------------------------
#define SMSH   72
#define PANELB (128 * SMSH * 2)
#define STAGEB (3 * PANELB)
#define GDYN   (2 * STAGEB)

__global__ void __launch_bounds__(256, 2) mma_gemm_kernel(
    const fp16* __restrict__ Ahi, const fp16* __restrict__ Alo,
    const fp16* __restrict__ Bw,  const fp16* __restrict__ Bw2,
    const float* __restrict__ bias, float* __restrict__ C, float* __restrict__ C2,
    int M, int N, int K)
{
    extern __shared__ fp16 smem_dyn[];
    const unsigned sbase = smem_u32(smem_dyn);

    const fp16* Bsel = (blockIdx.z == 0) ? Bw : Bw2;
    float*      Csel = (blockIdx.z == 0) ? C  : C2;

    const int tid  = threadIdx.x;
    const int warp = tid >> 5;
    const int lane = tid & 31;
    const int bm = blockIdx.y * 128;
    const int bn = blockIdx.x * 128;
    const int wm = (warp >> 1) * 32;
    const int wn = (warp & 1) * 64;

    unsigned dsta[4];
    int a_sz[4];
    size_t a_src[4], b_src[4];
#pragma unroll
    for (int j = 0; j < 4; j++) {
        int c   = tid + 256 * j;
        int row = c >> 3;
        int sl  = c & 7;
        dsta[j] = sbase + (unsigned)(row * SMSH + sl * 8) * 2;
        int gm = bm + row;
        a_sz[j]  = (gm < M) ? 16 : 0;
        int gm_c = (gm < M) ? gm : (M > 0 ? M - 1 : 0);
        a_src[j] = (size_t)gm_c * K + sl * 8;
        b_src[j] = (size_t)(bn + row) * K + sl * 8;
    }

    unsigned a_addr[2], b_addr[4];
#pragma unroll
    for (int i = 0; i < 2; i++) {
        int row = wm + i * 16 + (lane & 15);
        int ko  = (lane >> 4) * 8;
        a_addr[i] = sbase + (unsigned)(row * SMSH + ko) * 2;
    }
#pragma unroll
    for (int jp = 0; jp < 4; jp++) {
        int grp = lane >> 3, lr = lane & 7;
        int row = wn + jp * 16 + ((grp >> 1) * 8) + lr;
        int ko  = (grp & 1) * 8;
        b_addr[jp] = sbase + 2u * PANELB + (unsigned)(row * SMSH + ko) * 2;
    }

    float acc[2][8][4];
#pragma unroll
    for (int i = 0; i < 2; i++)
#pragma unroll
        for (int j = 0; j < 8; j++)
#pragma unroll
            for (int r = 0; r < 4; r++) acc[i][j][r] = 0.f;

    const int KT = K >> 6;

    auto load_stage = [&](int st, int kt) {
        const unsigned so = (unsigned)st * STAGEB;
        const int kb = kt * 64;
#pragma unroll
        for (int j = 0; j < 4; j++) {
            cpa16(dsta[j] + so,              Ahi  + a_src[j] + kb, a_sz[j]);
            cpa16(dsta[j] + so + PANELB,     Alo  + a_src[j] + kb, a_sz[j]);
            cpa16(dsta[j] + so + 2u*PANELB,  Bsel + b_src[j] + kb, 16);
        }
        asm volatile("cp.async.commit_group;\n");
    };

    load_stage(0, 0);

    for (int kt = 0; kt < KT; kt++) {
        asm volatile("cp.async.wait_group 0;\n" ::: "memory");
        __syncthreads();

        if (kt + 1 < KT) load_stage((kt + 1) & 1, kt + 1);

        const unsigned so = (unsigned)(kt & 1) * STAGEB;
#pragma unroll
        for (int ks = 0; ks < 4; ks++) {
            const unsigned kso = so + ks * 32;
            unsigned ah[2][4], al[2][4];
#pragma unroll
            for (int i = 0; i < 2; i++) {
                ldmx4(ah[i][0], ah[i][1], ah[i][2], ah[i][3], a_addr[i] + kso);
                ldmx4(al[i][0], al[i][1], al[i][2], al[i][3], a_addr[i] + kso + PANELB);
            }
#pragma unroll
            for (int jp = 0; jp < 4; jp++) {
                unsigned bw[2][2];
                ldmx4(bw[0][0], bw[0][1], bw[1][0], bw[1][1], b_addr[jp] + kso);
#pragma unroll
                for (int jj = 0; jj < 2; jj++) {
                    int j = jp * 2 + jj;
                    mma_f16(acc[0][j], ah[0], bw[jj]);
                    mma_f16(acc[1][j], ah[1], bw[jj]);
                }
#pragma unroll
                for (int jj = 0; jj < 2; jj++) {
                    int j = jp * 2 + jj;
                    mma_f16(acc[0][j], al[0], bw[jj]);
                    mma_f16(acc[1][j], al[1], bw[jj]);
                }
            }
        }
        __syncthreads();
    }

#pragma unroll
    for (int i = 0; i < 2; i++) {
        int r0 = bm + wm + i * 16 + (lane >> 2);
#pragma unroll
        for (int j = 0; j < 8; j++) {
            int col = bn + wn + j * 8 + (lane & 3) * 2;
            float b0 = bias ? bias[col] : 0.f;
            float b1 = bias ? bias[col + 1] : 0.f;
            if (r0 < M) {
                float2 v = make_float2(acc[i][j][0] + b0, acc[i][j][1] + b1);
                *(float2*)(Csel + (size_t)r0 * N + col) = v;
            }
            if (r0 + 8 < M) {
                float2 v = make_float2(acc[i][j][2] + b0, acc[i][j][3] + b1);
                *(float2*)(Csel + (size_t)(r0 + 8) * N + col) = v;
            }
        }
    }
}

// ---------------------------------------------------------------------------
// Adapter down-proj GEMM: H[M,64] = gelu( X[M,1280] @ dW[64,1280]^T + db )
// ---------------------------------------------------------------------------
#define BPANELB (64 * SMSH * 2)
#define STAGE_D (2 * PANELB + BPANELB)
#define GDYN_D  (2 * STAGE_D)

__global__ void __launch_bounds__(256, 2) adapter_down_kernel(
    const fp16* __restrict__ F0h, const fp16* __restrict__ F0l,
    const fp16* __restrict__ F1h, const fp16* __restrict__ F1l,
    const fp16* __restrict__ dw0, const fp16* __restrict__ dw1,
    const float* __restrict__ db0, const float* __restrict__ db1,
    fp16* __restrict__ Hbuf)
{
    extern __shared__ fp16 smem_dyn[];
    const unsigned sbase = smem_u32(smem_dyn);

    const int z = blockIdx.z;
    const fp16* Ah = z ? F1h : F0h;
    const fp16* Al = z ? F1l : F0l;
    const fp16* Bw = z ? dw1 : dw0;
    const float* db = z ? db1 : db0;
    fp16* Hout = Hbuf + (size_t)z * M_BS * RAD_;

    const int tid  = threadIdx.x;
    const int warp = tid >> 5;
    const int lane = tid & 31;
    const int bm = blockIdx.y * 128;
    const int K = D_;

    unsigned dsta[4];
    size_t a_src[4];
#pragma unroll
    for (int j = 0; j < 4; j++) {
        int c   = tid + 256 * j;
        int row = c >> 3;
        int sl  = c & 7;
        dsta[j] = sbase + (unsigned)(row * SMSH + sl * 8) * 2;
        a_src[j] = (size_t)(bm + row) * K + sl * 8;
    }
    unsigned dstb[2];
    size_t b_src[2];
#pragma unroll
    for (int j = 0; j < 2; j++) {
        int c   = tid + 256 * j;
        int row = c >> 3;
        int sl  = c & 7;
        dstb[j] = sbase + 2u * PANELB + (unsigned)(row * SMSH + sl * 8) * 2;
        b_src[j] = (size_t)row * K + sl * 8;
    }

    const int wm = (warp >> 1) * 32;
    const int wn = (warp & 1) * 32;

    unsigned a_addr[2], b_addr[2];
#pragma unroll
    for (int i = 0; i < 2; i++) {
        int row = wm + i * 16 + (lane & 15);
        int ko  = (lane >> 4) * 8;
        a_addr[i] = sbase + (unsigned)(row * SMSH + ko) * 2;
    }
#pragma unroll
    for (int jp = 0; jp < 2; jp++) {
        int grp = lane >> 3, lr = lane & 7;
        int row = wn + jp * 16 + ((grp >> 1) * 8) + lr;
        int ko  = (grp & 1) * 8;
        b_addr[jp] = sbase + 2u * PANELB + (unsigned)(row * SMSH + ko) * 2;
    }

    float acc[2][4][4];
#pragma unroll
    for (int i = 0; i < 2; i++)
#pragma unroll
        for (int j = 0; j < 4; j++)
#pragma unroll
            for (int r = 0; r < 4; r++) acc[i][j][r] = 0.f;

    const int KT = K >> 6;

    auto load_stage = [&](int st, int kt) {
        const unsigned so = (unsigned)st * STAGE_D;
        const int kb = kt * 64;
#pragma unroll
        for (int j = 0; j < 4; j++) {
            cpa16(dsta[j] + so,          Ah + a_src[j] + kb, 16);
            cpa16(dsta[j] + so + PANELB, Al + a_src[j] + kb, 16);
        }
#pragma unroll
        for (int j = 0; j < 2; j++)
            cpa16(dstb[j] + so, Bw + b_src[j] + kb, 16);
        asm volatile("cp.async.commit_group;\n");
    };

    load_stage(0, 0);

    for (int kt = 0; kt < KT; kt++) {
        asm volatile("cp.async.wait_group 0;\n" ::: "memory");
        __syncthreads();

        if (kt + 1 < KT) load_stage((kt + 1) & 1, kt + 1);

        const unsigned so = (unsigned)(kt & 1) * STAGE_D;
#pragma unroll
        for (int ks = 0; ks < 4; ks++) {
            const unsigned kso = so + ks * 32;
            unsigned ah[2][4], al[2][4];
#pragma unroll
            for (int i = 0; i < 2; i++) {
                ldmx4(ah[i][0], ah[i][1], ah[i][2], ah[i][3], a_addr[i] + kso);
                ldmx4(al[i][0], al[i][1], al[i][2], al[i][3], a_addr[i] + kso + PANELB);
            }
#pragma unroll
            for (int jp = 0; jp < 2; jp++) {
                unsigned bw[2][2];
                ldmx4(bw[0][0], bw[0][1], bw[1][0], bw[1][1], b_addr[jp] + kso);
#pragma unroll
                for (int jj = 0; jj < 2; jj++) {
                    int j = jp * 2 + jj;
                    mma_f16(acc[0][j], ah[0], bw[jj]);
                    mma_f16(acc[1][j], ah[1], bw[jj]);
                }
#pragma unroll
                for (int jj = 0; jj < 2; jj++) {
                    int j = jp * 2 + jj;
                    mma_f16(acc[0][j], al[0], bw[jj]);
                    mma_f16(acc[1][j], al[1], bw[jj]);
                }
            }
        }
        __syncthreads();
    }

#pragma unroll
    for (int i = 0; i < 2; i++) {
        int r0 = bm + wm + i * 16 + (lane >> 2);
#pragma unroll
        for (int j = 0; j < 4; j++) {
            int col = wn + j * 8 + (lane & 3) * 2;
            float b0 = db[col], b1 = db[col + 1];
            {
                float v0 = gelu_exact(acc[i][j][0] + b0);
                float v1 = gelu_exact(acc[i][j][1] + b1);
                __half2 hv = __floats2half2_rn(v0, v1);
                *(__half2*)(Hout + (size_t)r0 * RAD_ + col) = hv;
            }
            {
                float v0 = gelu_exact(acc[i][j][2] + b0);
                float v1 = gelu_exact(acc[i][j][3] + b1);
                __half2 hv = __floats2half2_rn(v0, v1);
                *(__half2*)(Hout + (size_t)(r0 + 8) * RAD_ + col) = hv;
            }
        }
    }
}

// ---------------------------------------------------------------------------
// Adapter up-proj GEMM: out[M,1280] = X + ( H[M,64] @ uW[1280,64]^T + ub )
// ---------------------------------------------------------------------------
__global__ void __launch_bounds__(256, 2) adapter_up_kernel(
    const fp16* __restrict__ Hbuf,
    const fp16* __restrict__ uw0, const fp16* __restrict__ uw1,
    const float* __restrict__ ub0, const float* __restrict__ ub1,
    const fp16* __restrict__ F0h, const fp16* __restrict__ F0l,
    const fp16* __restrict__ F1h, const fp16* __restrict__ F1l,
    float* __restrict__ out)
{
    __shared__ fp16 smem_up[2 * 128 * SMSH];
    const unsigned sbase = smem_u32(smem_up);

    const int z = blockIdx.z;
    const fp16* A  = Hbuf + (size_t)z * M_BS * RAD_;
    const fp16* Bw = z ? uw1 : uw0;
    const float* ub = z ? ub1 : ub0;
    const fp16* Fh = z ? F1h : F0h;
    const fp16* Fl = z ? F1l : F0l;
    float* C = out + (size_t)(z + 1) * OFF_;

    const int tid  = threadIdx.x;
    const int warp = tid >> 5;
    const int lane = tid & 31;
    const int bm = blockIdx.y * 128;
    const int bn = blockIdx.x * 128;

#pragma unroll
    for (int j = 0; j < 4; j++) {
        int c   = tid + 256 * j;
        int row = c >> 3;
        int sl  = c & 7;
        *(uint4*)(smem_up + row * SMSH + sl * 8) =
            *(const uint4*)(A + (size_t)(bm + row) * RAD_ + sl * 8);
        *(uint4*)(smem_up + 128 * SMSH + row * SMSH + sl * 8) =
            *(const uint4*)(Bw + (size_t)(bn + row) * RAD_ + sl * 8);
    }
    __syncthreads();

    const int wm = (warp >> 1) * 32;
    const int wn = (warp & 1) * 64;

    unsigned a_addr[2], b_addr[4];
#pragma unroll
    for (int i = 0; i < 2; i++) {
        int row = wm + i * 16 + (lane & 15);
        int ko  = (lane >> 4) * 8;
        a_addr[i] = sbase + (unsigned)(row * SMSH + ko) * 2;
    }
#pragma unroll
    for (int jp = 0; jp < 4; jp++) {
        int grp = lane >> 3, lr = lane & 7;
        int row = wn + jp * 16 + ((grp >> 1) * 8) + lr;
        int ko  = (grp & 1) * 8;
        b_addr[jp] = sbase + (unsigned)(128 * SMSH + row * SMSH + ko) * 2;
    }

    float acc[2][8][4];
#pragma unroll
    for (int i = 0; i < 2; i++)
#pragma unroll
        for (int j = 0; j < 8; j++)
#pragma unroll
            for (int r = 0; r < 4; r++) acc[i][j][r] = 0.f;

#pragma unroll
    for (int ks = 0; ks < 4; ks++) {
        const unsigned kso = ks * 32;
        unsigned ah[2][4];
#pragma unroll
        for (int i = 0; i < 2; i++)
            ldmx4(ah[i][0], ah[i][1], ah[i][2], ah[i][3], a_addr[i] + kso);
#pragma unroll
        for (int jp = 0; jp < 4; jp++) {
            unsigned bw[2][2];
            ldmx4(bw[0][0], bw[0][1], bw[1][0], bw[1][1], b_addr[jp] + kso);
#pragma unroll
            for (int jj = 0; jj < 2; jj++) {
                int j = jp * 2 + jj;
                mma_f16(acc[0][j], ah[0], bw[jj]);
                mma_f16(acc[1][j], ah[1], bw[jj]);
            }
        }
    }

#pragma unroll
    for (int i = 0; i < 2; i++) {
        int r0 = bm + wm + i * 16 + (lane >> 2);
#pragma unroll
        for (int j = 0; j < 8; j++) {
            int col = bn + wn + j * 8 + (lane & 3) * 2;
            float u0 = ub[col], u1 = ub[col + 1];
#pragma unroll
            for (int rr = 0; rr < 2; rr++) {
                int r = r0 + rr * 8;
                __half2 xh = *(const __half2*)(Fh + (size_t)r * D_ + col);
                __half2 xl = *(const __half2*)(Fl + (size_t)r * D_ + col);
                float x0 = __half2float(__low2half(xh)) + __half2float(__low2half(xl));
                float x1 = __half2float(__high2half(xh)) + __half2float(__high2half(xl));
                float2 v = make_float2(acc[i][j][rr*2+0] + u0 + x0,
                                       acc[i][j][rr*2+1] + u1 + x1);
                *(float2*)(C + (size_t)r * D_ + col) = v;
            }
        }
    }
}

// ---------------------------------------------------------------------------
// Attention, shuffle-free, fp16 K/V in smem, 2 CTAs/SM.
// qT stride QST=68 (pad 4) -> staging writes 4-way instead of 32-way conflicts;
// float4 reads stay aligned (sl4 % 4 == 0, 68 % 4 == 0).
// ---------------------------------------------------------------------------
template<int TKV>
__global__ void __launch_bounds__(256) attn_kernel_t(
    const float* __restrict__ q, const float* __restrict__ k,
    const float* __restrict__ v, const int* __restrict__ toks,
    int maybe64, fp16* __restrict__ outH, fp16* __restrict__ outL)
{
    constexpr int NS   = (TKV + 31) / 32;
    constexpr int TPAD = NS * 32;
    constexpr int HDP  = HD_ / 2;        // 80 d-pairs
    constexpr int QST  = 68;             // padded q stride (anti-conflict)

    extern __shared__ char smc[];
    fp16*  KtH = (fp16*)smc;                                   // [HDP][TPAD][2]
    fp16*  Vsh = (fp16*)(smc + HDP * TPAD * 4);                // [TKV][HD_]
    float* qT  = (float*)(smc + HDP * TPAD * 4 + TKV * HD_ * 2);
    float* Ps  = qT + HD_ * QST;

    const int b  = blockIdx.z;
    const int h  = blockIdx.y;
    const int s0 = blockIdx.x * 64;
    const int tid = threadIdx.x;
    const float scale = 0.07905694150420949f;
    const unsigned FULL = 0xffffffffu;

    int is64 = 0;
    if (toks && maybe64)
        is64 = (toks[1] == 0 && toks[3] == 0 && toks[5] == 0 && toks[7] == 0);

    // --- stage K (fp16, d-pair-major) and V (fp16, row-major) ---
    for (int i = tid; i < TKV * HD_; i += 256) {
        int t = i / HD_;
        int d = i - t * HD_;
        int trow = t;
        if (toks) trow = is64 ? toks[2 * t] : toks[t];
        size_t gidx = ((size_t)b * T_ + trow) * D_ + h * HD_ + d;
        KtH[(d >> 1) * (TPAD * 2) + t * 2 + (d & 1)] = __float2half_rn(k[gidx]);
        Vsh[i] = __float2half_rn(v[gidx]);
    }
    // zero-pad K for t in [TKV, TPAD)
    constexpr int PADW = TPAD - TKV;
    for (int i = tid; i < HD_ * PADW; i += 256) {
        int d = i / PADW;
        int t = TKV + (i - d * PADW);
        KtH[(d >> 1) * (TPAD * 2) + t * 2 + (d & 1)] = __float2half_rn(0.f);
    }
    // stage qT (pre-scaled): 64 rows x 160, stride QST
    {
        const float* qb = q + ((size_t)b * S_ + s0) * D_ + h * HD_;
        for (int i = tid; i < 64 * HD_; i += 256) {
            int r = i / HD_;
            int d = i - r * HD_;
            qT[d * QST + r] = qb[(size_t)r * D_ + d] * scale;
        }
    }
    __syncthreads();

    const int warp = tid >> 5;
    const int lane = tid & 31;
    float* Pw = Ps + warp * TPAD * 4;
    const __half2* Kt2 = (const __half2*)KtH;

#pragma unroll
    for (int g = 0; g < 2; g++) {
        const int sl4 = warp * 8 + g * 4;
        size_t base0 = ((size_t)b * S_ + s0 + sl4) * D_ + h * HD_;

        float sc[4][NS];
#pragma unroll
        for (int i = 0; i < 4; i++)
#pragma unroll
            for (int n = 0; n < NS; n++) sc[i][n] = 0.f;

#pragma unroll 2
        for (int dp = 0; dp < HDP; dp++) {
            float4 qa  = *(const float4*)(qT + (2 * dp)     * QST + sl4);
            float4 qb4 = *(const float4*)(qT + (2 * dp + 1) * QST + sl4);
            float2 kf[NS];
#pragma unroll
            for (int n = 0; n < NS; n++)
                kf[n] = __half22float2(Kt2[dp * TPAD + lane + 32 * n]);
#pragma unroll
            for (int n = 0; n < NS; n++) {
                sc[0][n] += qa.x * kf[n].x + qb4.x * kf[n].y;
                sc[1][n] += qa.y * kf[n].x + qb4.y * kf[n].y;
                sc[2][n] += qa.z * kf[n].x + qb4.z * kf[n].y;
                sc[3][n] += qa.w * kf[n].x + qb4.w * kf[n].y;
            }
        }

        // --- softmax over keys ---
        float m[4];
#pragma unroll
        for (int i = 0; i < 4; i++) {
            m[i] = -1e30f;
#pragma unroll
            for (int n = 0; n < NS; n++)
                if (n * 32 + lane < TKV) m[i] = fmaxf(m[i], sc[i][n]);
        }
#pragma unroll
        for (int off = 16; off; off >>= 1) {
#pragma unroll
            for (int i = 0; i < 4; i++)
                m[i] = fmaxf(m[i], __shfl_xor_sync(FULL, m[i], off));
        }
        float ssum[4];
#pragma unroll
        for (int i = 0; i < 4; i++) {
            ssum[i] = 0.f;
#pragma unroll
            for (int n = 0; n < NS; n++) {
                sc[i][n] = (n * 32 + lane < TKV) ? expf(sc[i][n] - m[i]) : 0.f;
                ssum[i] += sc[i][n];
            }
        }
#pragma unroll
        for (int off = 16; off; off >>= 1) {
#pragma unroll
            for (int i = 0; i < 4; i++)
                ssum[i] += __shfl_xor_sync(FULL, ssum[i], off);
        }
#pragma unroll
        for (int i = 0; i < 4; i++) {
            float inv = 1.f / ssum[i];
#pragma unroll
            for (int n = 0; n < NS; n++) sc[i][n] *= inv;
        }

        // --- publish P ---
#pragma unroll
        for (int n = 0; n < NS; n++) {
            int t = lane + 32 * n;
#pragma unroll
            for (int i = 0; i < 4; i++)
                Pw[t * 4 + i] = sc[i][n];
        }
        __syncwarp();

        // --- weighted V accumulation ---
        float o[4][5];
#pragma unroll
        for (int i = 0; i < 4; i++)
#pragma unroll
            for (int j = 0; j < 5; j++) o[i][j] = 0.f;

#pragma unroll 2
        for (int t = 0; t < TKV; t++) {
            float4 pv = *(const float4*)(Pw + t * 4);
            const fp16* vr = Vsh + t * HD_;
            float vv[5];
#pragma unroll
            for (int j = 0; j < 5; j++) vv[j] = __half2float(vr[lane + 32 * j]);
#pragma unroll
            for (int j = 0; j < 5; j++) {
                o[0][j] += pv.x * vv[j];
                o[1][j] += pv.y * vv[j];
                o[2][j] += pv.z * vv[j];
                o[3][j] += pv.w * vv[j];
            }
        }

#pragma unroll
        for (int i = 0; i < 4; i++) {
#pragma unroll
            for (int j = 0; j < 5; j++) {
                fp16 hh, ll; split_f16(o[i][j], hh, ll);
                outH[base0 + (size_t)i * D_ + lane + 32 * j] = hh;
                outL[base0 + (size_t)i * D_ + lane + 32 * j] = ll;
            }
        }
        __syncwarp();
    }
}

// per-instantiation dynamic smem size (bytes)
template<int TKV>
constexpr size_t attn_smem() {
    constexpr int NS   = (TKV + 31) / 32;
    constexpr int TPAD = NS * 32;
    return (size_t)(HD_ / 2) * TPAD * 4   // K half2
         + (size_t)TKV * HD_ * 2          // V fp16
         + (size_t)HD_ * 68 * 4           // qT fp32 (QST=68)
         + (size_t)8 * TPAD * 4 * 4;      // Ps fp32
}

// ---------------------------------------------------------------------------
// Launch
// ---------------------------------------------------------------------------
extern "C" void kernel_launch(void* const* d_in, const int* in_sizes, int n_in,
                              void* d_out, int out_size)
{
    const float* hs    = (const float*)d_in[0];
    const float* enc   = (const float*)d_in[1];
    const int*   e0    = (const int*)  d_in[2];
    const int*   e1    = (const int*)  d_in[3];
    const float* Wq    = (const float*)d_in[4];
    const float* Wk    = (const float*)d_in[5];
    const float* Wv    = (const float*)d_in[6];
    const float* Wo    = (const float*)d_in[7];
    const float* bo    = (const float*)d_in[8];
    const float* lkA   = (const float*)d_in[9];
    const float* lkB   = (const float*)d_in[10];
    const float* lvA   = (const float*)d_in[11];
    const float* lvB   = (const float*)d_in[12];
    const float* loA   = (const float*)d_in[13];
    const float* loB   = (const float*)d_in[14];
    const float* a0dW  = (const float*)d_in[15];
    const float* a0db  = (const float*)d_in[16];
    const float* a0uW  = (const float*)d_in[17];
    const float* a0ub  = (const float*)d_in[18];
    const float* a1dW  = (const float*)d_in[19];
    const float* a1db  = (const float*)d_in[20];
    const float* a1uW  = (const float*)d_in[21];
    const float* a1ub  = (const float*)d_in[22];

    float *qp, *kp, *vp;
    fp16 *hsh, *hsl, *fgh, *fgl, *f0h, *f0l, *f1h, *f1l, *ench, *encl;
    fp16 *wq, *wo, *wk, *wv, *dw0, *dw1, *uw0, *uw1, *Hb;
    cudaGetSymbolAddress((void**)&qp,   g_q);
    cudaGetSymbolAddress((void**)&kp,   g_k);
    cudaGetSymbolAddress((void**)&vp,   g_v);
    cudaGetSymbolAddress((void**)&hsh,  g_hs_hi);
    cudaGetSymbolAddress((void**)&hsl,  g_hs_lo);
    cudaGetSymbolAddress((void**)&fgh,  g_fg_hi);
    cudaGetSymbolAddress((void**)&fgl,  g_fg_lo);
    cudaGetSymbolAddress((void**)&f0h,  g_f0_hi);
    cudaGetSymbolAddress((void**)&f0l,  g_f0_lo);
    cudaGetSymbolAddress((void**)&f1h,  g_f1_hi);
    cudaGetSymbolAddress((void**)&f1l,  g_f1_lo);
    cudaGetSymbolAddress((void**)&ench, g_enc_hi);
    cudaGetSymbolAddress((void**)&encl, g_enc_lo);
    cudaGetSymbolAddress((void**)&wq,   g_wq);
    cudaGetSymbolAddress((void**)&wo,   g_wo);
    cudaGetSymbolAddress((void**)&wk,   g_wk);
    cudaGetSymbolAddress((void**)&wv,   g_wv);
    cudaGetSymbolAddress((void**)&dw0,  g_dw0);
    cudaGetSymbolAddress((void**)&dw1,  g_dw1);
    cudaGetSymbolAddress((void**)&uw0,  g_uw0);
    cudaGetSymbolAddress((void**)&uw1,  g_uw1);
    cudaGetSymbolAddress((void**)&Hb,   g_H);

    float* out = (float*)d_out;

    cudaFuncSetAttribute(mma_gemm_kernel,
                         cudaFuncAttributeMaxDynamicSharedMemorySize, GDYN);
    cudaFuncSetAttribute(adapter_down_kernel,
                         cudaFuncAttributeMaxDynamicSharedMemorySize, GDYN_D);
    cudaFuncSetAttribute(attn_kernel_t<77>,
                         cudaFuncAttributeMaxDynamicSharedMemorySize, (int)attn_smem<77>());
    cudaFuncSetAttribute(attn_kernel_t<8>,
                         cudaFuncAttributeMaxDynamicSharedMemorySize, (int)attn_smem<8>());
    cudaFuncSetAttribute(attn_kernel_t<12>,
                         cudaFuncAttributeMaxDynamicSharedMemorySize, (int)attn_smem<12>());

    // 1: fused prep
    long prep_blocks = (PREP_TOT + 255) / 256;
    prep_kernel<<<(unsigned)prep_blocks, 256>>>(
        hs, enc, Wq, a0dW, a1dW, a0uW, a1uW,
        Wk, lkA, lkB, Wv, lvA, lvB, Wo, loA, loB,
        hsh, hsl, ench, encl, wq, dw0, dw1, uw0, uw1, wk, wv, wo);

    // 2: q projection
    dim3 gq(D_ / 128, M_BS / 128, 1);
    mma_gemm_kernel<<<gq, 256, GDYN>>>(hsh, hsl, wq, nullptr, nullptr,
                                       qp, nullptr, M_BS, D_, D_);

    // 3: merged k+v projections
    dim3 gkv(D_ / 128, (M_BT + 127) / 128, 2);
    mma_gemm_kernel<<<gkv, 256, GDYN>>>(ench, encl, wk, wv, nullptr,
                                        kp, vp, M_BT, D_, DT_);

    // 4: global attention  <-- ncu capture slot
    dim3 ga(S_ / 64, H_, B_);
    attn_kernel_t<77><<<ga, 256, attn_smem<77>()>>>(
        qp, kp, vp, nullptr, 0, fgh, fgl);

    // 5-6: entity attentions
    attn_kernel_t<8><<<ga, 256, attn_smem<8>()>>>(
        qp, kp, vp, e0, 1, f0h, f0l);
    attn_kernel_t<12><<<ga, 256, attn_smem<12>()>>>(
        qp, kp, vp, e1, 0, f1h, f1l);

    // 7: adapter down
    dim3 gd(1, M_BS / 128, 2);
    adapter_down_kernel<<<gd, 256, GDYN_D>>>(f0h, f0l, f1h, f1l,
                                             dw0, dw1, a0db, a1db, Hb);

    // 8: adapter up
    dim3 gu(D_ / 128, M_BS / 128, 2);
    adapter_up_kernel<<<gu, 256>>>(Hb, uw0, uw1, a0ub, a1ub,
                                   f0h, f0l, f1h, f1l, out);

    // 9: output projection
    mma_gemm_kernel<<<gq, 256, GDYN>>>(fgh, fgl, wo, nullptr, bo,
                                       out, nullptr, M_BS, D_, D_);
}

// round 17
// speedup vs baseline: 1.1099x; 1.0246x over previous
#include <cuda_runtime.h>
#include <cuda_fp16.h>
#include <math.h>
#include <stdint.h>
#include <stddef.h>

// ---------------------------------------------------------------------------
// Problem constants
// ---------------------------------------------------------------------------
#define B_   4
#define S_   4096
#define T_   77
#define D_   1280
#define DT_  768
#define H_   8
#define HD_  160
#define RAD_ 64
#define M_BS (B_*S_)   // 16384
#define M_BT (B_*T_)   // 308
#define OFF_ ((size_t)M_BS * D_)

typedef __half fp16;

// ---------------------------------------------------------------------------
// Device scratch
// ---------------------------------------------------------------------------
__device__ float g_q  [M_BS * D_];
__device__ float g_k  [M_BT * D_];
__device__ float g_v  [M_BT * D_];

__device__ fp16 g_hs_hi [M_BS * D_];
__device__ fp16 g_hs_lo [M_BS * D_];
__device__ fp16 g_fg_hi [M_BS * D_];
__device__ fp16 g_fg_lo [M_BS * D_];
__device__ fp16 g_f0_hi [M_BS * D_];
__device__ fp16 g_f0_lo [M_BS * D_];
__device__ fp16 g_f1_hi [M_BS * D_];
__device__ fp16 g_f1_lo [M_BS * D_];
__device__ fp16 g_enc_hi[M_BT * DT_];
__device__ fp16 g_enc_lo[M_BT * DT_];
__device__ fp16 g_wq [D_ * D_];
__device__ fp16 g_wo [D_ * D_];
__device__ fp16 g_wk [D_ * DT_];
__device__ fp16 g_wv [D_ * DT_];
__device__ fp16 g_dw0[RAD_ * D_];
__device__ fp16 g_dw1[RAD_ * D_];
__device__ fp16 g_uw0[D_ * RAD_];
__device__ fp16 g_uw1[D_ * RAD_];
__device__ fp16 g_H  [2 * M_BS * RAD_];

// ---------------------------------------------------------------------------
// helpers
// ---------------------------------------------------------------------------
__device__ __forceinline__ unsigned smem_u32(const void* p) {
    return (unsigned)__cvta_generic_to_shared(p);
}
__device__ __forceinline__ void cpa16(unsigned dst, const fp16* src, int sz) {
    asm volatile("cp.async.cg.shared.global [%0], [%1], 16, %2;\n"
                 :: "r"(dst), "l"(src), "r"(sz));
}
__device__ __forceinline__ void ldmx4(unsigned& r0, unsigned& r1, unsigned& r2, unsigned& r3, unsigned addr) {
    asm volatile("ldmatrix.sync.aligned.m8n8.x4.shared.b16 {%0,%1,%2,%3}, [%4];"
                 : "=r"(r0), "=r"(r1), "=r"(r2), "=r"(r3) : "r"(addr));
}
__device__ __forceinline__ void mma_f16(float* d, const unsigned* a, const unsigned* b) {
    asm volatile(
        "mma.sync.aligned.m16n8k16.row.col.f32.f16.f16.f32 "
        "{%0,%1,%2,%3}, {%4,%5,%6,%7}, {%8,%9}, {%0,%1,%2,%3};"
        : "+f"(d[0]), "+f"(d[1]), "+f"(d[2]), "+f"(d[3])
        : "r"(a[0]), "r"(a[1]), "r"(a[2]), "r"(a[3]), "r"(b[0]), "r"(b[1]));
}
__device__ __forceinline__ void split_f16(float x, fp16& hi, fp16& lo) {
    hi = __float2half_rn(x);
    lo = __float2half_rn(x - __half2float(hi));
}
__device__ __forceinline__ float gelu_exact(float x) {
    return 0.5f * x * (1.f + erff(x * 0.7071067811865475f));
}

// ---------------------------------------------------------------------------
// prep: all converts + LoRA folds fused (region-dispatched)
// ---------------------------------------------------------------------------
#define HS_C   5242880L
#define ENC_C  59136L
#define WQ_C   409600L
#define AD_C   20480L
#define WK_N   983040L
#define WO_N   1638400L
#define PREP_TOT (HS_C + ENC_C + WQ_C + 4*AD_C + 2*WK_N + WO_N)

__device__ __forceinline__ void cvt2_v4(const float* x, fp16* hi, fp16* lo, long i) {
    float4 v = *(const float4*)(x + i);
    fp16 h0,l0,h1,l1,h2,l2,h3,l3;
    split_f16(v.x,h0,l0); split_f16(v.y,h1,l1); split_f16(v.z,h2,l2); split_f16(v.w,h3,l3);
    hi[i]=h0; hi[i+1]=h1; hi[i+2]=h2; hi[i+3]=h3;
    lo[i]=l0; lo[i+1]=l1; lo[i+2]=l2; lo[i+3]=l3;
}
__device__ __forceinline__ void cvt1_v4(const float* x, fp16* w, long i) {
    float4 v = *(const float4*)(x + i);
    w[i]   = __float2half_rn(v.x); w[i+1] = __float2half_rn(v.y);
    w[i+2] = __float2half_rn(v.z); w[i+3] = __float2half_rn(v.w);
}
__device__ __forceinline__ void fold1(const float* W, const float* A, const float* Bm,
                                      fp16* w, int K, long i) {
    int n = (int)(i / K);
    int k = (int)(i - (long)n * K);
    float acc = W[i];
#pragma unroll
    for (int r = 0; r < 4; r++)
        acc += 0.25f * Bm[n * 4 + r] * A[r * K + k];
    w[i] = __float2half_rn(acc);
}

__global__ void prep_kernel(
    const float* __restrict__ hs, const float* __restrict__ enc, const float* __restrict__ Wq,
    const float* __restrict__ a0dW, const float* __restrict__ a1dW,
    const float* __restrict__ a0uW, const float* __restrict__ a1uW,
    const float* __restrict__ Wk, const float* __restrict__ lkA, const float* __restrict__ lkB,
    const float* __restrict__ Wv, const float* __restrict__ lvA, const float* __restrict__ lvB,
    const float* __restrict__ Wo, const float* __restrict__ loA, const float* __restrict__ loB,
    fp16* hsh, fp16* hsl, fp16* ench, fp16* encl, fp16* wq,
    fp16* dw0, fp16* dw1, fp16* uw0, fp16* uw1,
    fp16* wk, fp16* wv, fp16* wo)
{
    long gid = (long)blockIdx.x * 256 + threadIdx.x;
    if (gid < HS_C)  { cvt2_v4(hs,  hsh,  hsl,  gid * 4); return; }
    gid -= HS_C;
    if (gid < ENC_C) { cvt2_v4(enc, ench, encl, gid * 4); return; }
    gid -= ENC_C;
    if (gid < WQ_C)  { cvt1_v4(Wq, wq, gid * 4); return; }
    gid -= WQ_C;
    if (gid < AD_C)  { cvt1_v4(a0dW, dw0, gid * 4); return; }
    gid -= AD_C;
    if (gid < AD_C)  { cvt1_v4(a1dW, dw1, gid * 4); return; }
    gid -= AD_C;
    if (gid < AD_C)  { cvt1_v4(a0uW, uw0, gid * 4); return; }
    gid -= AD_C;
    if (gid < AD_C)  { cvt1_v4(a1uW, uw1, gid * 4); return; }
    gid -= AD_C;
    if (gid < WK_N)  { fold1(Wk, lkA, lkB, wk, DT_, gid); return; }
    gid -= WK_N;
    if (gid < WK_N)  { fold1(Wv, lvA, lvB, wv, DT_, gid); return; }
    gid -= WK_N;
    if (gid < WO_N)  { fold1(Wo, loA, loB, wo, D_, gid); return; }
}

// ---------------------------------------------------------------------------
// Main tensor-core GEMM: C[M,N] = A[M,K] @ W[N,K]^T (+bias), 2-pass fp16 split
// ---------------------------------------------------------------------------
#define SMSH   72
#define PANELB (128 * SMSH * 2)
#define STAGEB (3 * PANELB)
#define GDYN   (2 * STAGEB)

__global__ void __launch_bounds__(256, 2) mma_gemm_kernel(
    const fp16* __restrict__ Ahi, const fp16* __restrict__ Alo,
    const fp16* __restrict__ Bw,  const fp16* __restrict__ Bw2,
    const float* __restrict__ bias, float* __restrict__ C, float* __restrict__ C2,
    int M, int N, int K)
{
    extern __shared__ fp16 smem_dyn[];
    const unsigned sbase = smem_u32(smem_dyn);

    const fp16* Bsel = (blockIdx.z == 0) ? Bw : Bw2;
    float*      Csel = (blockIdx.z == 0) ? C  : C2;

    const int tid  = threadIdx.x;
    const int warp = tid >> 5;
    const int lane = tid & 31;
    const int bm = blockIdx.y * 128;
    const int bn = blockIdx.x * 128;
    const int wm = (warp >> 1) * 32;
    const int wn = (warp & 1) * 64;

    unsigned dsta[4];
    int a_sz[4];
    size_t a_src[4], b_src[4];
#pragma unroll
    for (int j = 0; j < 4; j++) {
        int c   = tid + 256 * j;
        int row = c >> 3;
        int sl  = c & 7;
        dsta[j] = sbase + (unsigned)(row * SMSH + sl * 8) * 2;
        int gm = bm + row;
        a_sz[j]  = (gm < M) ? 16 : 0;
        int gm_c = (gm < M) ? gm : (M > 0 ? M - 1 : 0);
        a_src[j] = (size_t)gm_c * K + sl * 8;
        b_src[j] = (size_t)(bn + row) * K + sl * 8;
    }

    unsigned a_addr[2], b_addr[4];
#pragma unroll
    for (int i = 0; i < 2; i++) {
        int row = wm + i * 16 + (lane & 15);
        int ko  = (lane >> 4) * 8;
        a_addr[i] = sbase + (unsigned)(row * SMSH + ko) * 2;
    }
#pragma unroll
    for (int jp = 0; jp < 4; jp++) {
        int grp = lane >> 3, lr = lane & 7;
        int row = wn + jp * 16 + ((grp >> 1) * 8) + lr;
        int ko  = (grp & 1) * 8;
        b_addr[jp] = sbase + 2u * PANELB + (unsigned)(row * SMSH + ko) * 2;
    }

    float acc[2][8][4];
#pragma unroll
    for (int i = 0; i < 2; i++)
#pragma unroll
        for (int j = 0; j < 8; j++)
#pragma unroll
            for (int r = 0; r < 4; r++) acc[i][j][r] = 0.f;

    const int KT = K >> 6;

    auto load_stage = [&](int st, int kt) {
        const unsigned so = (unsigned)st * STAGEB;
        const int kb = kt * 64;
#pragma unroll
        for (int j = 0; j < 4; j++) {
            cpa16(dsta[j] + so,              Ahi  + a_src[j] + kb, a_sz[j]);
            cpa16(dsta[j] + so + PANELB,     Alo  + a_src[j] + kb, a_sz[j]);
            cpa16(dsta[j] + so + 2u*PANELB,  Bsel + b_src[j] + kb, 16);
        }
        asm volatile("cp.async.commit_group;\n");
    };

    load_stage(0, 0);

    for (int kt = 0; kt < KT; kt++) {
        asm volatile("cp.async.wait_group 0;\n" ::: "memory");
        __syncthreads();

        if (kt + 1 < KT) load_stage((kt + 1) & 1, kt + 1);

        const unsigned so = (unsigned)(kt & 1) * STAGEB;
#pragma unroll
        for (int ks = 0; ks < 4; ks++) {
            const unsigned kso = so + ks * 32;
            unsigned ah[2][4], al[2][4];
#pragma unroll
            for (int i = 0; i < 2; i++) {
                ldmx4(ah[i][0], ah[i][1], ah[i][2], ah[i][3], a_addr[i] + kso);
                ldmx4(al[i][0], al[i][1], al[i][2], al[i][3], a_addr[i] + kso + PANELB);
            }
#pragma unroll
            for (int jp = 0; jp < 4; jp++) {
                unsigned bw[2][2];
                ldmx4(bw[0][0], bw[0][1], bw[1][0], bw[1][1], b_addr[jp] + kso);
#pragma unroll
                for (int jj = 0; jj < 2; jj++) {
                    int j = jp * 2 + jj;
                    mma_f16(acc[0][j], ah[0], bw[jj]);
                    mma_f16(acc[1][j], ah[1], bw[jj]);
                }
#pragma unroll
                for (int jj = 0; jj < 2; jj++) {
                    int j = jp * 2 + jj;
                    mma_f16(acc[0][j], al[0], bw[jj]);
                    mma_f16(acc[1][j], al[1], bw[jj]);
                }
            }
        }
        __syncthreads();
    }

#pragma unroll
    for (int i = 0; i < 2; i++) {
        int r0 = bm + wm + i * 16 + (lane >> 2);
#pragma unroll
        for (int j = 0; j < 8; j++) {
            int col = bn + wn + j * 8 + (lane & 3) * 2;
            float b0 = bias ? bias[col] : 0.f;
            float b1 = bias ? bias[col + 1] : 0.f;
            if (r0 < M) {
                float2 v = make_float2(acc[i][j][0] + b0, acc[i][j][1] + b1);
                *(float2*)(Csel + (size_t)r0 * N + col) = v;
            }
            if (r0 + 8 < M) {
                float2 v = make_float2(acc[i][j][2] + b0, acc[i][j][3] + b1);
                *(float2*)(Csel + (size_t)(r0 + 8) * N + col) = v;
            }
        }
    }
}

// ---------------------------------------------------------------------------
// Adapter down-proj GEMM: H[M,64] = gelu( X[M,1280] @ dW[64,1280]^T + db )
// ---------------------------------------------------------------------------
#define BPANELB (64 * SMSH * 2)
#define STAGE_D (2 * PANELB + BPANELB)
#define GDYN_D  (2 * STAGE_D)

__global__ void __launch_bounds__(256, 2) adapter_down_kernel(
    const fp16* __restrict__ F0h, const fp16* __restrict__ F0l,
    const fp16* __restrict__ F1h, const fp16* __restrict__ F1l,
    const fp16* __restrict__ dw0, const fp16* __restrict__ dw1,
    const float* __restrict__ db0, const float* __restrict__ db1,
    fp16* __restrict__ Hbuf)
{
    extern __shared__ fp16 smem_dyn[];
    const unsigned sbase = smem_u32(smem_dyn);

    const int z = blockIdx.z;
    const fp16* Ah = z ? F1h : F0h;
    const fp16* Al = z ? F1l : F0l;
    const fp16* Bw = z ? dw1 : dw0;
    const float* db = z ? db1 : db0;
    fp16* Hout = Hbuf + (size_t)z * M_BS * RAD_;

    const int tid  = threadIdx.x;
    const int warp = tid >> 5;
    const int lane = tid & 31;
    const int bm = blockIdx.y * 128;
    const int K = D_;

    unsigned dsta[4];
    size_t a_src[4];
#pragma unroll
    for (int j = 0; j < 4; j++) {
        int c   = tid + 256 * j;
        int row = c >> 3;
        int sl  = c & 7;
        dsta[j] = sbase + (unsigned)(row * SMSH + sl * 8) * 2;
        a_src[j] = (size_t)(bm + row) * K + sl * 8;
    }
    unsigned dstb[2];
    size_t b_src[2];
#pragma unroll
    for (int j = 0; j < 2; j++) {
        int c   = tid + 256 * j;
        int row = c >> 3;
        int sl  = c & 7;
        dstb[j] = sbase + 2u * PANELB + (unsigned)(row * SMSH + sl * 8) * 2;
        b_src[j] = (size_t)row * K + sl * 8;
    }

    const int wm = (warp >> 1) * 32;
    const int wn = (warp & 1) * 32;

    unsigned a_addr[2], b_addr[2];
#pragma unroll
    for (int i = 0; i < 2; i++) {
        int row = wm + i * 16 + (lane & 15);
        int ko  = (lane >> 4) * 8;
        a_addr[i] = sbase + (unsigned)(row * SMSH + ko) * 2;
    }
#pragma unroll
    for (int jp = 0; jp < 2; jp++) {
        int grp = lane >> 3, lr = lane & 7;
        int row = wn + jp * 16 + ((grp >> 1) * 8) + lr;
        int ko  = (grp & 1) * 8;
        b_addr[jp] = sbase + 2u * PANELB + (unsigned)(row * SMSH + ko) * 2;
    }

    float acc[2][4][4];
#pragma unroll
    for (int i = 0; i < 2; i++)
#pragma unroll
        for (int j = 0; j < 4; j++)
#pragma unroll
            for (int r = 0; r < 4; r++) acc[i][j][r] = 0.f;

    const int KT = K >> 6;

    auto load_stage = [&](int st, int kt) {
        const unsigned so = (unsigned)st * STAGE_D;
        const int kb = kt * 64;
#pragma unroll
        for (int j = 0; j < 4; j++) {
            cpa16(dsta[j] + so,          Ah + a_src[j] + kb, 16);
            cpa16(dsta[j] + so + PANELB, Al + a_src[j] + kb, 16);
        }
#pragma unroll
        for (int j = 0; j < 2; j++)
            cpa16(dstb[j] + so, Bw + b_src[j] + kb, 16);
        asm volatile("cp.async.commit_group;\n");
    };

    load_stage(0, 0);

    for (int kt = 0; kt < KT; kt++) {
        asm volatile("cp.async.wait_group 0;\n" ::: "memory");
        __syncthreads();

        if (kt + 1 < KT) load_stage((kt + 1) & 1, kt + 1);

        const unsigned so = (unsigned)(kt & 1) * STAGE_D;
#pragma unroll
        for (int ks = 0; ks < 4; ks++) {
            const unsigned kso = so + ks * 32;
            unsigned ah[2][4], al[2][4];
#pragma unroll
            for (int i = 0; i < 2; i++) {
                ldmx4(ah[i][0], ah[i][1], ah[i][2], ah[i][3], a_addr[i] + kso);
                ldmx4(al[i][0], al[i][1], al[i][2], al[i][3], a_addr[i] + kso + PANELB);
            }
#pragma unroll
            for (int jp = 0; jp < 2; jp++) {
                unsigned bw[2][2];
                ldmx4(bw[0][0], bw[0][1], bw[1][0], bw[1][1], b_addr[jp] + kso);
#pragma unroll
                for (int jj = 0; jj < 2; jj++) {
                    int j = jp * 2 + jj;
                    mma_f16(acc[0][j], ah[0], bw[jj]);
                    mma_f16(acc[1][j], ah[1], bw[jj]);
                }
#pragma unroll
                for (int jj = 0; jj < 2; jj++) {
                    int j = jp * 2 + jj;
                    mma_f16(acc[0][j], al[0], bw[jj]);
                    mma_f16(acc[1][j], al[1], bw[jj]);
                }
            }
        }
        __syncthreads();
    }

#pragma unroll
    for (int i = 0; i < 2; i++) {
        int r0 = bm + wm + i * 16 + (lane >> 2);
#pragma unroll
        for (int j = 0; j < 4; j++) {
            int col = wn + j * 8 + (lane & 3) * 2;
            float b0 = db[col], b1 = db[col + 1];
            {
                float v0 = gelu_exact(acc[i][j][0] + b0);
                float v1 = gelu_exact(acc[i][j][1] + b1);
                __half2 hv = __floats2half2_rn(v0, v1);
                *(__half2*)(Hout + (size_t)r0 * RAD_ + col) = hv;
            }
            {
                float v0 = gelu_exact(acc[i][j][2] + b0);
                float v1 = gelu_exact(acc[i][j][3] + b1);
                __half2 hv = __floats2half2_rn(v0, v1);
                *(__half2*)(Hout + (size_t)(r0 + 8) * RAD_ + col) = hv;
            }
        }
    }
}

// ---------------------------------------------------------------------------
// Adapter up-proj GEMM: out[M,1280] = X + ( H[M,64] @ uW[1280,64]^T + ub )
// ---------------------------------------------------------------------------
__global__ void __launch_bounds__(256, 2) adapter_up_kernel(
    const fp16* __restrict__ Hbuf,
    const fp16* __restrict__ uw0, const fp16* __restrict__ uw1,
    const float* __restrict__ ub0, const float* __restrict__ ub1,
    const fp16* __restrict__ F0h, const fp16* __restrict__ F0l,
    const fp16* __restrict__ F1h, const fp16* __restrict__ F1l,
    float* __restrict__ out)
{
    __shared__ fp16 smem_up[2 * 128 * SMSH];
    const unsigned sbase = smem_u32(smem_up);

    const int z = blockIdx.z;
    const fp16* A  = Hbuf + (size_t)z * M_BS * RAD_;
    const fp16* Bw = z ? uw1 : uw0;
    const float* ub = z ? ub1 : ub0;
    const fp16* Fh = z ? F1h : F0h;
    const fp16* Fl = z ? F1l : F0l;
    float* C = out + (size_t)(z + 1) * OFF_;

    const int tid  = threadIdx.x;
    const int warp = tid >> 5;
    const int lane = tid & 31;
    const int bm = blockIdx.y * 128;
    const int bn = blockIdx.x * 128;

#pragma unroll
    for (int j = 0; j < 4; j++) {
        int c   = tid + 256 * j;
        int row = c >> 3;
        int sl  = c & 7;
        *(uint4*)(smem_up + row * SMSH + sl * 8) =
            *(const uint4*)(A + (size_t)(bm + row) * RAD_ + sl * 8);
        *(uint4*)(smem_up + 128 * SMSH + row * SMSH + sl * 8) =
            *(const uint4*)(Bw + (size_t)(bn + row) * RAD_ + sl * 8);
    }
    __syncthreads();

    const int wm = (warp >> 1) * 32;
    const int wn = (warp & 1) * 64;

    unsigned a_addr[2], b_addr[4];
#pragma unroll
    for (int i = 0; i < 2; i++) {
        int row = wm + i * 16 + (lane & 15);
        int ko  = (lane >> 4) * 8;
        a_addr[i] = sbase + (unsigned)(row * SMSH + ko) * 2;
    }
#pragma unroll
    for (int jp = 0; jp < 4; jp++) {
        int grp = lane >> 3, lr = lane & 7;
        int row = wn + jp * 16 + ((grp >> 1) * 8) + lr;
        int ko  = (grp & 1) * 8;
        b_addr[jp] = sbase + (unsigned)(128 * SMSH + row * SMSH + ko) * 2;
    }

    float acc[2][8][4];
#pragma unroll
    for (int i = 0; i < 2; i++)
#pragma unroll
        for (int j = 0; j < 8; j++)
#pragma unroll
            for (int r = 0; r < 4; r++) acc[i][j][r] = 0.f;

#pragma unroll
    for (int ks = 0; ks < 4; ks++) {
        const unsigned kso = ks * 32;
        unsigned ah[2][4];
#pragma unroll
        for (int i = 0; i < 2; i++)
            ldmx4(ah[i][0], ah[i][1], ah[i][2], ah[i][3], a_addr[i] + kso);
#pragma unroll
        for (int jp = 0; jp < 4; jp++) {
            unsigned bw[2][2];
            ldmx4(bw[0][0], bw[0][1], bw[1][0], bw[1][1], b_addr[jp] + kso);
#pragma unroll
            for (int jj = 0; jj < 2; jj++) {
                int j = jp * 2 + jj;
                mma_f16(acc[0][j], ah[0], bw[jj]);
                mma_f16(acc[1][j], ah[1], bw[jj]);
            }
        }
    }

#pragma unroll
    for (int i = 0; i < 2; i++) {
        int r0 = bm + wm + i * 16 + (lane >> 2);
#pragma unroll
        for (int j = 0; j < 8; j++) {
            int col = bn + wn + j * 8 + (lane & 3) * 2;
            float u0 = ub[col], u1 = ub[col + 1];
#pragma unroll
            for (int rr = 0; rr < 2; rr++) {
                int r = r0 + rr * 8;
                __half2 xh = *(const __half2*)(Fh + (size_t)r * D_ + col);
                __half2 xl = *(const __half2*)(Fl + (size_t)r * D_ + col);
                float x0 = __half2float(__low2half(xh)) + __half2float(__low2half(xl));
                float x1 = __half2float(__high2half(xh)) + __half2float(__high2half(xl));
                float2 v = make_float2(acc[i][j][rr*2+0] + u0 + x0,
                                       acc[i][j][rr*2+1] + u1 + x1);
                *(float2*)(C + (size_t)r * D_ + col) = v;
            }
        }
    }
}

// ---------------------------------------------------------------------------
// Global attention (TKV=77): shuffle-free, fp16 K/V in smem, 2 CTAs/SM.
// qT stride QST=68 (anti-conflict); float4 reads aligned.
// ---------------------------------------------------------------------------
template<int TKV>
__global__ void __launch_bounds__(256) attn_kernel_t(
    const float* __restrict__ q, const float* __restrict__ k,
    const float* __restrict__ v, const int* __restrict__ toks,
    int maybe64, fp16* __restrict__ outH, fp16* __restrict__ outL)
{
    constexpr int NS   = (TKV + 31) / 32;
    constexpr int TPAD = NS * 32;
    constexpr int HDP  = HD_ / 2;
    constexpr int QST  = 68;

    extern __shared__ char smc[];
    fp16*  KtH = (fp16*)smc;
    fp16*  Vsh = (fp16*)(smc + HDP * TPAD * 4);
    float* qT  = (float*)(smc + HDP * TPAD * 4 + TKV * HD_ * 2);
    float* Ps  = qT + HD_ * QST;

    const int b  = blockIdx.z;
    const int h  = blockIdx.y;
    const int s0 = blockIdx.x * 64;
    const int tid = threadIdx.x;
    const float scale = 0.07905694150420949f;
    const unsigned FULL = 0xffffffffu;

    int is64 = 0;
    if (toks && maybe64)
        is64 = (toks[1] == 0 && toks[3] == 0 && toks[5] == 0 && toks[7] == 0);

    for (int i = tid; i < TKV * HD_; i += 256) {
        int t = i / HD_;
        int d = i - t * HD_;
        int trow = t;
        if (toks) trow = is64 ? toks[2 * t] : toks[t];
        size_t gidx = ((size_t)b * T_ + trow) * D_ + h * HD_ + d;
        KtH[(d >> 1) * (TPAD * 2) + t * 2 + (d & 1)] = __float2half_rn(k[gidx]);
        Vsh[i] = __float2half_rn(v[gidx]);
    }
    constexpr int PADW = TPAD - TKV;
    for (int i = tid; i < HD_ * PADW; i += 256) {
        int d = i / PADW;
        int t = TKV + (i - d * PADW);
        KtH[(d >> 1) * (TPAD * 2) + t * 2 + (d & 1)] = __float2half_rn(0.f);
    }
    {
        const float* qb = q + ((size_t)b * S_ + s0) * D_ + h * HD_;
        for (int i = tid; i < 64 * HD_; i += 256) {
            int r = i / HD_;
            int d = i - r * HD_;
            qT[d * QST + r] = qb[(size_t)r * D_ + d] * scale;
        }
    }
    __syncthreads();

    const int warp = tid >> 5;
    const int lane = tid & 31;
    float* Pw = Ps + warp * TPAD * 4;
    const __half2* Kt2 = (const __half2*)KtH;

#pragma unroll
    for (int g = 0; g < 2; g++) {
        const int sl4 = warp * 8 + g * 4;
        size_t base0 = ((size_t)b * S_ + s0 + sl4) * D_ + h * HD_;

        float sc[4][NS];
#pragma unroll
        for (int i = 0; i < 4; i++)
#pragma unroll
            for (int n = 0; n < NS; n++) sc[i][n] = 0.f;

#pragma unroll 2
        for (int dp = 0; dp < HDP; dp++) {
            float4 qa  = *(const float4*)(qT + (2 * dp)     * QST + sl4);
            float4 qb4 = *(const float4*)(qT + (2 * dp + 1) * QST + sl4);
            float2 kf[NS];
#pragma unroll
            for (int n = 0; n < NS; n++)
                kf[n] = __half22float2(Kt2[dp * TPAD + lane + 32 * n]);
#pragma unroll
            for (int n = 0; n < NS; n++) {
                sc[0][n] += qa.x * kf[n].x + qb4.x * kf[n].y;
                sc[1][n] += qa.y * kf[n].x + qb4.y * kf[n].y;
                sc[2][n] += qa.z * kf[n].x + qb4.z * kf[n].y;
                sc[3][n] += qa.w * kf[n].x + qb4.w * kf[n].y;
            }
        }

        float m[4];
#pragma unroll
        for (int i = 0; i < 4; i++) {
            m[i] = -1e30f;
#pragma unroll
            for (int n = 0; n < NS; n++)
                if (n * 32 + lane < TKV) m[i] = fmaxf(m[i], sc[i][n]);
        }
#pragma unroll
        for (int off = 16; off; off >>= 1) {
#pragma unroll
            for (int i = 0; i < 4; i++)
                m[i] = fmaxf(m[i], __shfl_xor_sync(FULL, m[i], off));
        }
        float ssum[4];
#pragma unroll
        for (int i = 0; i < 4; i++) {
            ssum[i] = 0.f;
#pragma unroll
            for (int n = 0; n < NS; n++) {
                sc[i][n] = (n * 32 + lane < TKV) ? expf(sc[i][n] - m[i]) : 0.f;
                ssum[i] += sc[i][n];
            }
        }
#pragma unroll
        for (int off = 16; off; off >>= 1) {
#pragma unroll
            for (int i = 0; i < 4; i++)
                ssum[i] += __shfl_xor_sync(FULL, ssum[i], off);
        }
#pragma unroll
        for (int i = 0; i < 4; i++) {
            float inv = 1.f / ssum[i];
#pragma unroll
            for (int n = 0; n < NS; n++) sc[i][n] *= inv;
        }

#pragma unroll
        for (int n = 0; n < NS; n++) {
            int t = lane + 32 * n;
#pragma unroll
            for (int i = 0; i < 4; i++)
                Pw[t * 4 + i] = sc[i][n];
        }
        __syncwarp();

        float o[4][5];
#pragma unroll
        for (int i = 0; i < 4; i++)
#pragma unroll
            for (int j = 0; j < 5; j++) o[i][j] = 0.f;

#pragma unroll 2
        for (int t = 0; t < TKV; t++) {
            float4 pv = *(const float4*)(Pw + t * 4);
            const fp16* vr = Vsh + t * HD_;
            float vv[5];
#pragma unroll
            for (int j = 0; j < 5; j++) vv[j] = __half2float(vr[lane + 32 * j]);
#pragma unroll
            for (int j = 0; j < 5; j++) {
                o[0][j] += pv.x * vv[j];
                o[1][j] += pv.y * vv[j];
                o[2][j] += pv.z * vv[j];
                o[3][j] += pv.w * vv[j];
            }
        }

#pragma unroll
        for (int i = 0; i < 4; i++) {
#pragma unroll
            for (int j = 0; j < 5; j++) {
                fp16 hh, ll; split_f16(o[i][j], hh, ll);
                outH[base0 + (size_t)i * D_ + lane + 32 * j] = hh;
                outL[base0 + (size_t)i * D_ + lane + 32 * j] = ll;
            }
        }
        __syncwarp();
    }
}

template<int TKV>
constexpr size_t attn_smem() {
    constexpr int NS   = (TKV + 31) / 32;
    constexpr int TPAD = NS * 32;
    return (size_t)(HD_ / 2) * TPAD * 4
         + (size_t)TKV * HD_ * 2
         + (size_t)HD_ * 68 * 4
         + (size_t)8 * TPAD * 4 * 4;
}

// ---------------------------------------------------------------------------
// Entity attention (TKV<=32): R12-style 4-query-batched shuffle kernel.
// Tiny smem (fp32 K/V rows) -> high occupancy; shfl cost small at 8-12 keys.
// ---------------------------------------------------------------------------
template<int TKV>
__global__ void __launch_bounds__(256) attn_small_t(
    const float* __restrict__ q, const float* __restrict__ k,
    const float* __restrict__ v, const int* __restrict__ toks,
    int maybe64, fp16* __restrict__ outH, fp16* __restrict__ outL)
{
    static_assert(TKV <= 32, "attn_small_t requires TKV <= 32");
    extern __shared__ float sm[];
    float* Ks = sm;
    float* Vs = sm + TKV * HD_;

    const int b  = blockIdx.z;
    const int h  = blockIdx.y;
    const int s0 = blockIdx.x * 64;
    const int tid = threadIdx.x;

    int is64 = 0;
    if (toks && maybe64)
        is64 = (toks[1] == 0 && toks[3] == 0 && toks[5] == 0 && toks[7] == 0);

    for (int i = tid; i < TKV * HD_; i += 256) {
        int t = i / HD_;
        int d = i - t * HD_;
        int trow = is64 ? toks[2 * t] : toks[t];
        size_t gidx = ((size_t)b * T_ + trow) * D_ + h * HD_ + d;
        Ks[i] = k[gidx];
        Vs[i] = v[gidx];
    }
    __syncthreads();

    const int warp = tid >> 5;
    const int lane = tid & 31;
    const float scale = 0.07905694150420949f;
    const unsigned FULL = 0xffffffffu;

#pragma unroll
    for (int g = 0; g < 2; g++) {
        const int s = s0 + warp * 8 + g * 4;
        size_t base0 = ((size_t)b * S_ + s) * D_ + h * HD_;

        float qr[4][5];
#pragma unroll
        for (int i = 0; i < 4; i++)
#pragma unroll
            for (int j = 0; j < 5; j++)
                qr[i][j] = q[base0 + (size_t)i * D_ + lane + 32 * j];

        float sc[4];
#pragma unroll
        for (int i = 0; i < 4; i++) sc[i] = 0.f;

#pragma unroll
        for (int t = 0; t < TKV; t++) {
            const float* kr = Ks + t * HD_;
            float kv_[5];
#pragma unroll
            for (int j = 0; j < 5; j++) kv_[j] = kr[lane + 32 * j];

            float p[4];
#pragma unroll
            for (int i = 0; i < 4; i++) {
                p[i] = 0.f;
#pragma unroll
                for (int j = 0; j < 5; j++) p[i] += qr[i][j] * kv_[j];
            }
#pragma unroll
            for (int off = 16; off; off >>= 1) {
#pragma unroll
                for (int i = 0; i < 4; i++)
                    p[i] += __shfl_xor_sync(FULL, p[i], off);
            }
            if (t == lane) {
#pragma unroll
                for (int i = 0; i < 4; i++) sc[i] = p[i] * scale;
            }
        }

        float m[4];
#pragma unroll
        for (int i = 0; i < 4; i++)
            m[i] = (lane < TKV) ? sc[i] : -1e30f;
#pragma unroll
        for (int off = 16; off; off >>= 1) {
#pragma unroll
            for (int i = 0; i < 4; i++)
                m[i] = fmaxf(m[i], __shfl_xor_sync(FULL, m[i], off));
        }
        float ssum[4];
#pragma unroll
        for (int i = 0; i < 4; i++) {
            sc[i] = (lane < TKV) ? expf(sc[i] - m[i]) : 0.f;
            ssum[i] = sc[i];
        }
#pragma unroll
        for (int off = 16; off; off >>= 1) {
#pragma unroll
            for (int i = 0; i < 4; i++)
                ssum[i] += __shfl_xor_sync(FULL, ssum[i], off);
        }
#pragma unroll
        for (int i = 0; i < 4; i++) sc[i] *= 1.f / ssum[i];

        float o[4][5];
#pragma unroll
        for (int i = 0; i < 4; i++)
#pragma unroll
            for (int j = 0; j < 5; j++) o[i][j] = 0.f;

#pragma unroll
        for (int t = 0; t < TKV; t++) {
            const float* vr = Vs + t * HD_;
            float vv[5];
#pragma unroll
            for (int j = 0; j < 5; j++) vv[j] = vr[lane + 32 * j];
            float p[4];
#pragma unroll
            for (int i = 0; i < 4; i++)
                p[i] = __shfl_sync(FULL, sc[i], t);
#pragma unroll
            for (int i = 0; i < 4; i++)
#pragma unroll
                for (int j = 0; j < 5; j++) o[i][j] += p[i] * vv[j];
        }

#pragma unroll
        for (int i = 0; i < 4; i++) {
#pragma unroll
            for (int j = 0; j < 5; j++) {
                fp16 hh, ll; split_f16(o[i][j], hh, ll);
                outH[base0 + (size_t)i * D_ + lane + 32 * j] = hh;
                outL[base0 + (size_t)i * D_ + lane + 32 * j] = ll;
            }
        }
    }
}

// ---------------------------------------------------------------------------
// Launch
// ---------------------------------------------------------------------------
extern "C" void kernel_launch(void* const* d_in, const int* in_sizes, int n_in,
                              void* d_out, int out_size)
{
    const float* hs    = (const float*)d_in[0];
    const float* enc   = (const float*)d_in[1];
    const int*   e0    = (const int*)  d_in[2];
    const int*   e1    = (const int*)  d_in[3];
    const float* Wq    = (const float*)d_in[4];
    const float* Wk    = (const float*)d_in[5];
    const float* Wv    = (const float*)d_in[6];
    const float* Wo    = (const float*)d_in[7];
    const float* bo    = (const float*)d_in[8];
    const float* lkA   = (const float*)d_in[9];
    const float* lkB   = (const float*)d_in[10];
    const float* lvA   = (const float*)d_in[11];
    const float* lvB   = (const float*)d_in[12];
    const float* loA   = (const float*)d_in[13];
    const float* loB   = (const float*)d_in[14];
    const float* a0dW  = (const float*)d_in[15];
    const float* a0db  = (const float*)d_in[16];
    const float* a0uW  = (const float*)d_in[17];
    const float* a0ub  = (const float*)d_in[18];
    const float* a1dW  = (const float*)d_in[19];
    const float* a1db  = (const float*)d_in[20];
    const float* a1uW  = (const float*)d_in[21];
    const float* a1ub  = (const float*)d_in[22];

    float *qp, *kp, *vp;
    fp16 *hsh, *hsl, *fgh, *fgl, *f0h, *f0l, *f1h, *f1l, *ench, *encl;
    fp16 *wq, *wo, *wk, *wv, *dw0, *dw1, *uw0, *uw1, *Hb;
    cudaGetSymbolAddress((void**)&qp,   g_q);
    cudaGetSymbolAddress((void**)&kp,   g_k);
    cudaGetSymbolAddress((void**)&vp,   g_v);
    cudaGetSymbolAddress((void**)&hsh,  g_hs_hi);
    cudaGetSymbolAddress((void**)&hsl,  g_hs_lo);
    cudaGetSymbolAddress((void**)&fgh,  g_fg_hi);
    cudaGetSymbolAddress((void**)&fgl,  g_fg_lo);
    cudaGetSymbolAddress((void**)&f0h,  g_f0_hi);
    cudaGetSymbolAddress((void**)&f0l,  g_f0_lo);
    cudaGetSymbolAddress((void**)&f1h,  g_f1_hi);
    cudaGetSymbolAddress((void**)&f1l,  g_f1_lo);
    cudaGetSymbolAddress((void**)&ench, g_enc_hi);
    cudaGetSymbolAddress((void**)&encl, g_enc_lo);
    cudaGetSymbolAddress((void**)&wq,   g_wq);
    cudaGetSymbolAddress((void**)&wo,   g_wo);
    cudaGetSymbolAddress((void**)&wk,   g_wk);
    cudaGetSymbolAddress((void**)&wv,   g_wv);
    cudaGetSymbolAddress((void**)&dw0,  g_dw0);
    cudaGetSymbolAddress((void**)&dw1,  g_dw1);
    cudaGetSymbolAddress((void**)&uw0,  g_uw0);
    cudaGetSymbolAddress((void**)&uw1,  g_uw1);
    cudaGetSymbolAddress((void**)&Hb,   g_H);

    float* out = (float*)d_out;

    cudaFuncSetAttribute(mma_gemm_kernel,
                         cudaFuncAttributeMaxDynamicSharedMemorySize, GDYN);
    cudaFuncSetAttribute(adapter_down_kernel,
                         cudaFuncAttributeMaxDynamicSharedMemorySize, GDYN_D);
    cudaFuncSetAttribute(attn_kernel_t<77>,
                         cudaFuncAttributeMaxDynamicSharedMemorySize, (int)attn_smem<77>());

    // 1: fused prep
    long prep_blocks = (PREP_TOT + 255) / 256;
    prep_kernel<<<(unsigned)prep_blocks, 256>>>(
        hs, enc, Wq, a0dW, a1dW, a0uW, a1uW,
        Wk, lkA, lkB, Wv, lvA, lvB, Wo, loA, loB,
        hsh, hsl, ench, encl, wq, dw0, dw1, uw0, uw1, wk, wv, wo);

    // 2: q projection
    dim3 gq(D_ / 128, M_BS / 128, 1);
    mma_gemm_kernel<<<gq, 256, GDYN>>>(hsh, hsl, wq, nullptr, nullptr,
                                       qp, nullptr, M_BS, D_, D_);

    // 3: merged k+v projections
    dim3 gkv(D_ / 128, (M_BT + 127) / 128, 2);
    mma_gemm_kernel<<<gkv, 256, GDYN>>>(ench, encl, wk, wv, nullptr,
                                        kp, vp, M_BT, D_, DT_);

    // 4: global attention (shuffle-free)  <-- ncu capture slot
    dim3 ga(S_ / 64, H_, B_);
    attn_kernel_t<77><<<ga, 256, attn_smem<77>()>>>(
        qp, kp, vp, nullptr, 0, fgh, fgl);

    // 5-6: entity attentions (shuffle kernel, tiny smem, high occupancy)
    attn_small_t<8><<<ga, 256, (size_t)8 * HD_ * 2 * sizeof(float)>>>(
        qp, kp, vp, e0, 1, f0h, f0l);
    attn_small_t<12><<<ga, 256, (size_t)12 * HD_ * 2 * sizeof(float)>>>(
        qp, kp, vp, e1, 0, f1h, f1l);

    // 7: adapter down
    dim3 gd(1, M_BS / 128, 2);
    adapter_down_kernel<<<gd, 256, GDYN_D>>>(f0h, f0l, f1h, f1l,
                                             dw0, dw1, a0db, a1db, Hb);

    // 8: adapter up
    dim3 gu(D_ / 128, M_BS / 128, 2);
    adapter_up_kernel<<<gu, 256>>>(Hb, uw0, uw1, a0ub, a1ub,
                                   f0h, f0l, f1h, f1l, out);

    // 9: output projection
    mma_gemm_kernel<<<gq, 256, GDYN>>>(fgh, fgl, wo, nullptr, bo,
                                       out, nullptr, M_BS, D_, D_);
}